// round 14
// baseline (speedup 1.0000x reference)
#include <cuda_runtime.h>
#include <cuda_fp16.h>
#include <math.h>
#include <cstdint>

// ---------------------------------------------------------------------------
// Problem constants
// ---------------------------------------------------------------------------
#define BATCH   2
#define SEQ     2048
#define DMODEL  1024
#define NHEADS  16
#define HEADDIM 64
#define DFF     4096
#define TOKENS  (BATCH * SEQ)          // 4096

// ---------------------------------------------------------------------------
// Scratch (static device allocations)
// ---------------------------------------------------------------------------
__device__ __half g_srch[TOKENS * DMODEL];
__device__ __half g_qh  [TOKENS * DMODEL];
__device__ __half g_kh  [TOKENS * DMODEL];
__device__ __half g_vh  [TOKENS * DMODEL];
__device__ __half g_ctxh[TOKENS * DMODEL];
__device__ __half g_h1h [TOKENS * DMODEL];
__device__ __half g_f1h [(size_t)TOKENS * DFF];
__device__ __half g_aoh [TOKENS * DMODEL];
__device__ __half g_f2h2[TOKENS * DMODEL];
__device__ float  g_h1f [TOKENS * DMODEL];
// half weights, natural [K][N] layout
__device__ __half g_wqH[DMODEL * DMODEL];
__device__ __half g_wkH[DMODEL * DMODEL];
__device__ __half g_wvH[DMODEL * DMODEL];
__device__ __half g_woH[DMODEL * DMODEL];
__device__ __half g_w1H[(size_t)DMODEL * DFF];
__device__ __half g_w2H[(size_t)DFF * DMODEL];

// ---------------------------------------------------------------------------
// PTX helpers
// ---------------------------------------------------------------------------
__device__ __forceinline__ uint32_t smem_u32(const void* p) {
    return (uint32_t)__cvta_generic_to_shared(p);
}
__device__ __forceinline__ void cp16(uint32_t s, const void* g) {
    asm volatile("cp.async.cg.shared.global [%0], [%1], 16;" :: "r"(s), "l"(g));
}
__device__ __forceinline__ void cp_commit() {
    asm volatile("cp.async.commit_group;");
}
template<int N>
__device__ __forceinline__ void cp_wait() {
    asm volatile("cp.async.wait_group %0;" :: "n"(N));
}
__device__ __forceinline__ uint32_t pack2(float lo, float hi) {
    __half2 h = __floats2half2_rn(lo, hi);
    return *reinterpret_cast<uint32_t*>(&h);
}
__device__ __forceinline__ void ldsm4(uint32_t addr, uint32_t* r) {
    asm volatile("ldmatrix.sync.aligned.m8n8.x4.shared.b16 {%0,%1,%2,%3}, [%4];"
        : "=r"(r[0]), "=r"(r[1]), "=r"(r[2]), "=r"(r[3]) : "r"(addr));
}
__device__ __forceinline__ void ldsm4t(uint32_t addr, uint32_t* r) {
    asm volatile("ldmatrix.sync.aligned.m8n8.x4.trans.shared.b16 {%0,%1,%2,%3}, [%4];"
        : "=r"(r[0]), "=r"(r[1]), "=r"(r[2]), "=r"(r[3]) : "r"(addr));
}
__device__ __forceinline__ void mma_f16(float* c, const uint32_t* a, const uint32_t* b) {
    asm volatile(
        "mma.sync.aligned.m16n8k16.row.col.f32.f16.f16.f32 "
        "{%0,%1,%2,%3}, {%4,%5,%6,%7}, {%8,%9}, {%0,%1,%2,%3};"
        : "+f"(c[0]), "+f"(c[1]), "+f"(c[2]), "+f"(c[3])
        : "r"(a[0]), "r"(a[1]), "r"(a[2]), "r"(a[3]), "r"(b[0]), "r"(b[1]));
}

// ---------------------------------------------------------------------------
// FP16 GEMM v3: C[M,N] = A[M,K](half) @ W[K,N](half) + bias.
// BM=64, BN=256, BK=32, 4 warps, WARP TILE 64x64 (high smem reuse:
// ~105 B of smem traffic per mma vs 262 before), 3-stage ring, 3 CTAs/SM.
// No cross-stage fragment prefetch (race-free by construction).
// ---------------------------------------------------------------------------
#define GM_ASTR 40                       // A smem row stride (halves)
#define GM_BSTR 264                      // B smem row stride (halves)
#define GM_AH   (64 * GM_ASTR)           // 2560 halves
#define GM_BH   (32 * GM_BSTR)           // 8448 halves
#define GM_STG  (GM_AH + GM_BH)          // 11008 halves / stage
#define GM_SMEM_BYTES (3 * GM_STG * 2)   // 66048 (x3 CTAs = 193.5 KB/SM)

template<bool QKV, bool GELU>
__global__ __launch_bounds__(128, 3)
void hgemm(int M, int N, int K,
           const __half* __restrict__ A,
           const __half* __restrict__ W0, const __half* __restrict__ W1_,
           const __half* __restrict__ W2_,
           __half* __restrict__ Ch0, __half* __restrict__ Ch1,
           __half* __restrict__ Ch2,
           int ldc,
           const float* __restrict__ bias0, const float* __restrict__ bias1,
           const float* __restrict__ bias2,
           const float* __restrict__ tau)
{
    extern __shared__ __half hsm[];

    const __half* W    = W0;
    __half*       Ch   = Ch0;
    const float*  bias = bias0;
    bool rope = false;
    float oscale = 1.0f;
    if (QKV) {
        int z = blockIdx.z;
        if (z == 1)      { W = W1_; Ch = Ch1; bias = bias1; }
        else if (z == 2) { W = W2_; Ch = Ch2; bias = bias2; }
        rope = (z < 2);
        if (z == 0) oscale = 0.125f;
    }

    const int tid  = threadIdx.x;
    const int lane = tid & 31;
    const int warp = tid >> 5;            // 0..3
    const int grp  = lane >> 2;
    const int tig  = lane & 3;
    const int wn0  = warp * 64;           // warp tile 64(M) x 64(N)
    const int m0 = blockIdx.y * 64;
    const int n0 = blockIdx.x * 256;

    const uint32_t sbase = smem_u32(hsm);
    const uint32_t aOff = ((lane & 15) * GM_ASTR + (lane >> 4) * 8) * 2;
    const int g8 = lane >> 3, r8 = lane & 7;
    const uint32_t bOff = (((g8 & 1) * 8 + r8) * GM_BSTR + wn0 + (g8 >> 1) * 8) * 2;

    float acc[4][8][4];
#pragma unroll
    for (int mi = 0; mi < 4; mi++)
#pragma unroll
        for (int ni = 0; ni < 8; ni++)
#pragma unroll
            for (int e = 0; e < 4; e++) acc[mi][ni][e] = 0.0f;

    auto stage_base = [&](int s) -> uint32_t {
        return sbase + (uint32_t)(s % 3) * (GM_STG * 2);
    };

    auto load_stage = [&](int s) {
        uint32_t ab = stage_base(s);
        uint32_t bb = ab + GM_AH * 2;
        int k0 = s * 32;
        // A: 64 rows x 32 halves = 256 x 16B chunks, 2/thread
#pragma unroll
        for (int l = 0; l < 2; l++) {
            int c = tid + l * 128;
            int m = c >> 2, ch = c & 3;
            cp16(ab + (m * GM_ASTR + ch * 8) * 2,
                 A + (size_t)(m0 + m) * K + k0 + ch * 8);
        }
        // B: 32 rows x 256 halves = 1024 x 16B chunks, 8/thread
#pragma unroll
        for (int l = 0; l < 8; l++) {
            int c = tid + l * 128;
            int kk = c >> 5, nq = c & 31;
            cp16(bb + (kk * GM_BSTR + nq * 8) * 2,
                 W + (size_t)(k0 + kk) * N + n0 + nq * 8);
        }
        cp_commit();
    };

    auto compute_stage = [&](int s) {
        uint32_t ab = stage_base(s);
        uint32_t bb = ab + GM_AH * 2;
#pragma unroll
        for (int kk = 0; kk < 32; kk += 16) {
            uint32_t af[4][4], bf[8][2];
#pragma unroll
            for (int mi = 0; mi < 4; mi++)
                ldsm4(ab + aOff + (mi * 16 * GM_ASTR + kk) * 2, af[mi]);
#pragma unroll
            for (int nip = 0; nip < 4; nip++)
                ldsm4t(bb + bOff + (kk * GM_BSTR + nip * 16) * 2, &bf[2 * nip][0]);
#pragma unroll
            for (int mi = 0; mi < 4; mi++)
#pragma unroll
                for (int ni = 0; ni < 8; ni++)
                    mma_f16(acc[mi][ni], af[mi], bf[ni]);
        }
    };

    const int S = K / 32;
    load_stage(0); load_stage(1);
    for (int s = 0; s < S; s++) {
        // stage s must be complete. committed = min(s+2, S) groups;
        // pending <= (committed - (s+1)) -> wait<1> steady, wait<0> tail.
        if (s <= S - 2) cp_wait<1>();
        else            cp_wait<0>();
        __syncthreads();              // visibility + ring-slot (s%3) reuse
        if (s + 2 < S) load_stage(s + 2);
        compute_stage(s);
    }

    // ---- epilogue (half output) ----
#pragma unroll
    for (int mi = 0; mi < 4; mi++) {
#pragma unroll
        for (int h = 0; h < 2; h++) {
            int row = m0 + mi * 16 + grp + h * 8;
            float t = 0.0f;
            if (QKV) t = tau[row];
#pragma unroll
            for (int ni = 0; ni < 8; ni++) {
                int gcol = n0 + wn0 + ni * 8 + 2 * tig;
                float v0 = acc[mi][ni][h * 2 + 0];
                float v1 = acc[mi][ni][h * 2 + 1];
                if (bias) { v0 += bias[gcol]; v1 += bias[gcol + 1]; }
                if (GELU) {
                    v0 = 0.5f * v0 * (1.0f + erff(v0 * 0.7071067811865475f));
                    v1 = 0.5f * v1 * (1.0f + erff(v1 * 0.7071067811865475f));
                }
                if (QKV && rope) {
                    int j = (gcol & 63) >> 1;
                    float inv = __expf(-0.28782313662425572f * (float)j);
                    float sn, cs;
                    sincosf(t * inv, &sn, &cs);
                    float r0 = v0 * cs - v1 * sn;
                    float r1 = v1 * cs + v0 * sn;
                    v0 = r0 * oscale; v1 = r1 * oscale;
                }
                *(__half2*)(Ch + (size_t)row * ldc + gcol) =
                    __floats2half2_rn(v0, v1);
            }
        }
    }
}

// ---------------------------------------------------------------------------
// Fused float->half conversion of all 7 buffers in one launch.
// ---------------------------------------------------------------------------
struct F2HJob {
    const float4* in[7];
    __half2*      out[7];
    int           end[7];   // cumulative end offsets (in float4 units)
};

__global__ __launch_bounds__(256)
void f2h_all_kernel(F2HJob job)
{
    int i = blockIdx.x * 256 + threadIdx.x;
    int seg = 0, base = 0;
#pragma unroll
    for (int s = 0; s < 7; s++) {
        if (i >= job.end[s]) { seg = s + 1; base = job.end[s]; }
    }
    if (seg >= 7) return;
    int off = i - base;
    float4 v = job.in[seg][off];
    job.out[seg][2 * off]     = __floats2half2_rn(v.x, v.y);
    job.out[seg][2 * off + 1] = __floats2half2_rn(v.z, v.w);
}

// ---------------------------------------------------------------------------
// FP16 flash attention with ldmatrix + cp.async K/V double buffers.
// ---------------------------------------------------------------------------
#define FK_STR  72
#define FT_H    (128 * FK_STR)
#define FA_SMEM_BYTES (4 * FT_H * 2)      // 73728

__global__ __launch_bounds__(256)
void flash_kernel(const __half* __restrict__ q, const __half* __restrict__ k,
                  const __half* __restrict__ v, __half* __restrict__ ctx)
{
    extern __shared__ __half fsm[];
    const uint32_t sbase = smem_u32(fsm);

    const int tid  = threadIdx.x;
    const int lane = tid & 31;
    const int warp = tid >> 5;
    const int grp  = lane >> 2;
    const int tig  = lane & 3;
    const int g8 = lane >> 3, r8 = lane & 7;

    const int m0 = blockIdx.x * 128;
    const int bh = blockIdx.y;
    const int b  = bh >> 4;
    const int h  = bh & 15;

    const __half* qb = q + ((size_t)b * SEQ) * DMODEL + h * HEADDIM;
    const __half* kb = k + ((size_t)b * SEQ) * DMODEL + h * HEADDIM;
    const __half* vb = v + ((size_t)b * SEQ) * DMODEL + h * HEADDIM;

    const uint32_t qOff = ((warp * 16 + (lane & 15)) * FK_STR + (lane >> 4) * 8) * 2;
    const uint32_t kOff = ((r8 + (g8 >> 1) * 8) * FK_STR + (g8 & 1) * 8) * 2;
    const uint32_t vOff = ((r8 + (g8 & 1) * 8) * FK_STR + (g8 >> 1) * 8) * 2;

#pragma unroll
    for (int l = 0; l < 4; l++) {
        int c = tid + l * 256;
        int r = c >> 3, ch = c & 7;
        cp16(sbase + (r * FK_STR + ch * 8) * 2,
             qb + (size_t)(m0 + r) * DMODEL + ch * 8);
    }
    cp_commit(); cp_wait<0>(); __syncthreads();

    uint32_t aq[4][4];
#pragma unroll
    for (int kc = 0; kc < 4; kc++)
        ldsm4(sbase + qOff + kc * 32, aq[kc]);
    __syncthreads();

    float o[8][4];
#pragma unroll
    for (int ni = 0; ni < 8; ni++)
#pragma unroll
        for (int e = 0; e < 4; e++) o[ni][e] = 0.0f;
    float mrun0 = -1e30f, mrun1 = -1e30f, lrun0 = 0.0f, lrun1 = 0.0f;

    auto load_kv = [&](int t) {
        uint32_t kd = sbase + (t & 1) * FT_H * 2;
        uint32_t vd = sbase + (2 + (t & 1)) * FT_H * 2;
#pragma unroll
        for (int l = 0; l < 4; l++) {
            int c = tid + l * 256;
            int r = c >> 3, ch = c & 7;
            uint32_t so = (r * FK_STR + ch * 8) * 2;
            size_t  go = (size_t)(t * 128 + r) * DMODEL + ch * 8;
            cp16(kd + so, kb + go);
            cp16(vd + so, vb + go);
        }
        cp_commit();
    };

    load_kv(0);

    const int NTILE = SEQ / 128;
    for (int t = 0; t < NTILE; t++) {
        cp_wait<0>();
        __syncthreads();
        if (t + 1 < NTILE) load_kv(t + 1);

        uint32_t kbuf = sbase + (t & 1) * FT_H * 2;
        uint32_t vbuf = sbase + (2 + (t & 1)) * FT_H * 2;

        float sacc[16][4];
#pragma unroll
        for (int ni = 0; ni < 16; ni++)
#pragma unroll
            for (int e = 0; e < 4; e++) sacc[ni][e] = 0.0f;

        // ---- S = Q @ K^T, pipelined ----
        {
            uint32_t bf2[2][4];
            ldsm4(kbuf + kOff, bf2[0]);
#pragma unroll
            for (int it = 0; it < 32; it++) {
                if (it + 1 < 32) {
                    int kc2 = (it + 1) >> 3, nip2 = (it + 1) & 7;
                    ldsm4(kbuf + kOff + (nip2 * 16 * FK_STR + kc2 * 16) * 2,
                          bf2[(it + 1) & 1]);
                }
                int kc = it >> 3, nip = it & 7;
                mma_f16(sacc[2 * nip    ], aq[kc], &bf2[it & 1][0]);
                mma_f16(sacc[2 * nip + 1], aq[kc], &bf2[it & 1][2]);
            }
        }

        float tmax0 = -1e30f, tmax1 = -1e30f;
#pragma unroll
        for (int ni = 0; ni < 16; ni++) {
            tmax0 = fmaxf(tmax0, fmaxf(sacc[ni][0], sacc[ni][1]));
            tmax1 = fmaxf(tmax1, fmaxf(sacc[ni][2], sacc[ni][3]));
        }
        tmax0 = fmaxf(tmax0, __shfl_xor_sync(0xffffffffu, tmax0, 1));
        tmax0 = fmaxf(tmax0, __shfl_xor_sync(0xffffffffu, tmax0, 2));
        tmax1 = fmaxf(tmax1, __shfl_xor_sync(0xffffffffu, tmax1, 1));
        tmax1 = fmaxf(tmax1, __shfl_xor_sync(0xffffffffu, tmax1, 2));

        float nm0 = fmaxf(mrun0, tmax0);
        float nm1 = fmaxf(mrun1, tmax1);
        float sc0 = __expf(mrun0 - nm0);
        float sc1 = __expf(mrun1 - nm1);
        mrun0 = nm0; mrun1 = nm1;

        float sum0 = 0.0f, sum1 = 0.0f;
#pragma unroll
        for (int ni = 0; ni < 16; ni++) {
            sacc[ni][0] = __expf(sacc[ni][0] - nm0);
            sacc[ni][1] = __expf(sacc[ni][1] - nm0);
            sacc[ni][2] = __expf(sacc[ni][2] - nm1);
            sacc[ni][3] = __expf(sacc[ni][3] - nm1);
            sum0 += sacc[ni][0] + sacc[ni][1];
            sum1 += sacc[ni][2] + sacc[ni][3];
        }
        sum0 += __shfl_xor_sync(0xffffffffu, sum0, 1);
        sum0 += __shfl_xor_sync(0xffffffffu, sum0, 2);
        sum1 += __shfl_xor_sync(0xffffffffu, sum1, 1);
        sum1 += __shfl_xor_sync(0xffffffffu, sum1, 2);
        lrun0 = lrun0 * sc0 + sum0;
        lrun1 = lrun1 * sc1 + sum1;

#pragma unroll
        for (int ni = 0; ni < 8; ni++) {
            o[ni][0] *= sc0; o[ni][1] *= sc0;
            o[ni][2] *= sc1; o[ni][3] *= sc1;
        }

        uint32_t pA[8][4];
#pragma unroll
        for (int kc = 0; kc < 8; kc++) {
            pA[kc][0] = pack2(sacc[2 * kc    ][0], sacc[2 * kc    ][1]);
            pA[kc][1] = pack2(sacc[2 * kc    ][2], sacc[2 * kc    ][3]);
            pA[kc][2] = pack2(sacc[2 * kc + 1][0], sacc[2 * kc + 1][1]);
            pA[kc][3] = pack2(sacc[2 * kc + 1][2], sacc[2 * kc + 1][3]);
        }

        // ---- O += P @ V, pipelined ----
        {
            uint32_t bb2[2][4];
            ldsm4t(vbuf + vOff, bb2[0]);
#pragma unroll
            for (int it = 0; it < 32; it++) {
                if (it + 1 < 32) {
                    int kc2 = (it + 1) >> 2, nip2 = (it + 1) & 3;
                    ldsm4t(vbuf + vOff + (kc2 * 16 * FK_STR + nip2 * 16) * 2,
                           bb2[(it + 1) & 1]);
                }
                int kc = it >> 2, nip = it & 3;
                mma_f16(o[2 * nip    ], pA[kc], &bb2[it & 1][0]);
                mma_f16(o[2 * nip + 1], pA[kc], &bb2[it & 1][2]);
            }
        }
    }

    float inv0 = 1.0f / lrun0;
    float inv1 = 1.0f / lrun1;
    int r0 = m0 + warp * 16 + grp;
    __half* cb = ctx + ((size_t)b * SEQ) * DMODEL + h * HEADDIM;
#pragma unroll
    for (int ni = 0; ni < 8; ni++) {
        int col = ni * 8 + 2 * tig;
        *(__half2*)(cb + (size_t)(r0    ) * DMODEL + col) =
            __floats2half2_rn(o[ni][0] * inv0, o[ni][1] * inv0);
        *(__half2*)(cb + (size_t)(r0 + 8) * DMODEL + col) =
            __floats2half2_rn(o[ni][2] * inv1, o[ni][3] * inv1);
    }
}

// ---------------------------------------------------------------------------
// Fused residual + LayerNorm: out = LN(a + b) * g + be.
// a is fp32 (residual), b is half (GEMM branch output).
// ---------------------------------------------------------------------------
__global__ __launch_bounds__(256)
void ln_kernel(const float* __restrict__ a, const __half* __restrict__ b,
               const float* __restrict__ g, const float* __restrict__ be,
               float* __restrict__ out, __half* __restrict__ outh)
{
    const int D = DMODEL;
    size_t row = blockIdx.x;
    const float*  pa = a + row * D;
    const __half* pb = b + row * D;
    int tid = threadIdx.x;
    __shared__ float red[256];

    float x[4];
    float s = 0.0f;
#pragma unroll
    for (int i = 0; i < 4; i++) {
        int c = tid + i * 256;
        x[i] = pa[c] + __half2float(pb[c]);
        s += x[i];
    }
    red[tid] = s;
    __syncthreads();
    for (int t = 128; t > 0; t >>= 1) {
        if (tid < t) red[tid] += red[tid + t];
        __syncthreads();
    }
    float mu = red[0] * (1.0f / D);
    __syncthreads();

    float v = 0.0f;
#pragma unroll
    for (int i = 0; i < 4; i++) {
        float d = x[i] - mu;
        v += d * d;
    }
    red[tid] = v;
    __syncthreads();
    for (int t = 128; t > 0; t >>= 1) {
        if (tid < t) red[tid] += red[tid + t];
        __syncthreads();
    }
    float var = red[0] * (1.0f / D);
    float r = rsqrtf(var + 1e-5f);
#pragma unroll
    for (int i = 0; i < 4; i++) {
        int c = tid + i * 256;
        float y = (x[i] - mu) * r * g[c] + be[c];
        out[row * D + c] = y;
        if (outh) outh[row * D + c] = __float2half_rn(y);
    }
}

// ---------------------------------------------------------------------------
// Host-side launch
// ---------------------------------------------------------------------------
static void* symptr_v(const void* sym)
{
    void* p = nullptr;
    cudaGetSymbolAddress(&p, sym);
    return p;
}

extern "C" void kernel_launch(void* const* d_in, const int* in_sizes, int n_in,
                              void* d_out, int out_size)
{
    const float* src = (const float*)d_in[0];
    const float* tau = (const float*)d_in[1];
    const float* Wq  = (const float*)d_in[2];
    const float* bq  = (const float*)d_in[3];
    const float* Wk  = (const float*)d_in[4];
    const float* bk  = (const float*)d_in[5];
    const float* Wv  = (const float*)d_in[6];
    const float* bv  = (const float*)d_in[7];
    const float* Wo  = (const float*)d_in[8];
    const float* bo  = (const float*)d_in[9];
    const float* W1  = (const float*)d_in[10];
    const float* b1  = (const float*)d_in[11];
    const float* W2  = (const float*)d_in[12];
    const float* b2  = (const float*)d_in[13];
    const float* g1  = (const float*)d_in[14];
    const float* be1 = (const float*)d_in[15];
    const float* g2  = (const float*)d_in[16];
    const float* be2 = (const float*)d_in[17];
    float* out = (float*)d_out;

    __half* srch = (__half*)symptr_v(g_srch);
    __half* qh   = (__half*)symptr_v(g_qh);
    __half* kh   = (__half*)symptr_v(g_kh);
    __half* vh   = (__half*)symptr_v(g_vh);
    __half* ctxh = (__half*)symptr_v(g_ctxh);
    __half* h1h  = (__half*)symptr_v(g_h1h);
    __half* f1h  = (__half*)symptr_v(g_f1h);
    __half* aoh  = (__half*)symptr_v(g_aoh);
    __half* f2h  = (__half*)symptr_v(g_f2h2);
    float*  h1f  = (float*)symptr_v(g_h1f);
    __half* wqH  = (__half*)symptr_v(g_wqH);
    __half* wkH  = (__half*)symptr_v(g_wkH);
    __half* wvH  = (__half*)symptr_v(g_wvH);
    __half* woH  = (__half*)symptr_v(g_woH);
    __half* w1H  = (__half*)symptr_v(g_w1H);
    __half* w2H  = (__half*)symptr_v(g_w2H);

    cudaFuncSetAttribute(flash_kernel,
                         cudaFuncAttributeMaxDynamicSharedMemorySize, FA_SMEM_BYTES);
    cudaFuncSetAttribute(hgemm<true,  false>,
                         cudaFuncAttributeMaxDynamicSharedMemorySize, GM_SMEM_BYTES);
    cudaFuncSetAttribute(hgemm<false, false>,
                         cudaFuncAttributeMaxDynamicSharedMemorySize, GM_SMEM_BYTES);
    cudaFuncSetAttribute(hgemm<false, true>,
                         cudaFuncAttributeMaxDynamicSharedMemorySize, GM_SMEM_BYTES);

    // ---- prep: single fused f2h of all weights + src ----
    {
        const int nW = DMODEL * DMODEL / 4;        // 262144
        const int nF = DMODEL * DFF / 4;           // 1048576
        const int nS = TOKENS * DMODEL / 4;        // 1048576
        F2HJob job;
        job.in[0] = (const float4*)Wq;  job.out[0] = (__half2*)wqH;
        job.in[1] = (const float4*)Wk;  job.out[1] = (__half2*)wkH;
        job.in[2] = (const float4*)Wv;  job.out[2] = (__half2*)wvH;
        job.in[3] = (const float4*)Wo;  job.out[3] = (__half2*)woH;
        job.in[4] = (const float4*)W1;  job.out[4] = (__half2*)w1H;
        job.in[5] = (const float4*)W2;  job.out[5] = (__half2*)w2H;
        job.in[6] = (const float4*)src; job.out[6] = (__half2*)srch;
        int acc = 0;
        int sizes[7] = { nW, nW, nW, nW, nF, nF, nS };
        for (int s = 0; s < 7; s++) { acc += sizes[s]; job.end[s] = acc; }
        f2h_all_kernel<<<(acc + 255) / 256, 256>>>(job);
    }

    // ---- QKV (+RoPE, q pre-scaled) ----
    hgemm<true, false>
        <<<dim3(DMODEL / 256, TOKENS / 64, 3), 128, GM_SMEM_BYTES>>>(
        TOKENS, DMODEL, DMODEL, srch, wqH, wkH, wvH,
        qh, kh, vh, DMODEL, bq, bk, bv, tau);

    // ---- flash attention -> ctx (half) ----
    flash_kernel<<<dim3(SEQ / 128, BATCH * NHEADS), 256, FA_SMEM_BYTES>>>(
        qh, kh, vh, ctxh);

    // ---- output projection -> aoh (half) ----
    hgemm<false, false>
        <<<dim3(DMODEL / 256, TOKENS / 64, 1), 128, GM_SMEM_BYTES>>>(
        TOKENS, DMODEL, DMODEL, ctxh, woH, nullptr, nullptr,
        aoh, nullptr, nullptr, DMODEL, bo, nullptr, nullptr, nullptr);

    // ---- LN1 -> h1 (fp32 + half) ----
    ln_kernel<<<TOKENS, 256>>>(src, aoh, g1, be1, h1f, h1h);

    // ---- FFN1 (GELU) -> f1 (half) ----
    hgemm<false, true>
        <<<dim3(DFF / 256, TOKENS / 64, 1), 128, GM_SMEM_BYTES>>>(
        TOKENS, DFF, DMODEL, h1h, w1H, nullptr, nullptr,
        f1h, nullptr, nullptr, DFF, b1, nullptr, nullptr, nullptr);

    // ---- FFN2 -> f2 (half) ----
    hgemm<false, false>
        <<<dim3(DMODEL / 256, TOKENS / 64, 1), 128, GM_SMEM_BYTES>>>(
        TOKENS, DMODEL, DFF, f1h, w2H, nullptr, nullptr,
        f2h, nullptr, nullptr, DMODEL, b2, nullptr, nullptr, nullptr);

    // ---- LN2 -> out ----
    ln_kernel<<<TOKENS, 256>>>(h1f, f2h, g2, be2, out, nullptr);

    (void)in_sizes; (void)n_in; (void)out_size;
}

// round 15
// speedup vs baseline: 1.1876x; 1.1876x over previous
#include <cuda_runtime.h>
#include <cuda_fp16.h>
#include <math.h>
#include <cstdint>

// ---------------------------------------------------------------------------
// Problem constants
// ---------------------------------------------------------------------------
#define BATCH   2
#define SEQ     2048
#define DMODEL  1024
#define NHEADS  16
#define HEADDIM 64
#define DFF     4096
#define TOKENS  (BATCH * SEQ)          // 4096

// ---------------------------------------------------------------------------
// Scratch (static device allocations)
// ---------------------------------------------------------------------------
__device__ __half g_srch[TOKENS * DMODEL];
__device__ __half g_qh  [TOKENS * DMODEL];
__device__ __half g_kh  [TOKENS * DMODEL];
__device__ __half g_vh  [TOKENS * DMODEL];
__device__ __half g_ctxh[TOKENS * DMODEL];
__device__ __half g_h1h [TOKENS * DMODEL];
__device__ __half g_f1h [(size_t)TOKENS * DFF];
__device__ __half g_aoh [TOKENS * DMODEL];
__device__ __half g_f2h2[TOKENS * DMODEL];
__device__ float  g_h1f [TOKENS * DMODEL];
// half weights, natural [K][N] layout
__device__ __half g_wqH[DMODEL * DMODEL];
__device__ __half g_wkH[DMODEL * DMODEL];
__device__ __half g_wvH[DMODEL * DMODEL];
__device__ __half g_woH[DMODEL * DMODEL];
__device__ __half g_w1H[(size_t)DMODEL * DFF];
__device__ __half g_w2H[(size_t)DFF * DMODEL];

// ---------------------------------------------------------------------------
// PTX helpers
// ---------------------------------------------------------------------------
__device__ __forceinline__ uint32_t smem_u32(const void* p) {
    return (uint32_t)__cvta_generic_to_shared(p);
}
__device__ __forceinline__ void cp16(uint32_t s, const void* g) {
    asm volatile("cp.async.cg.shared.global [%0], [%1], 16;" :: "r"(s), "l"(g));
}
__device__ __forceinline__ void cp_commit() {
    asm volatile("cp.async.commit_group;");
}
template<int N>
__device__ __forceinline__ void cp_wait() {
    asm volatile("cp.async.wait_group %0;" :: "n"(N));
}
__device__ __forceinline__ uint32_t pack2(float lo, float hi) {
    __half2 h = __floats2half2_rn(lo, hi);
    return *reinterpret_cast<uint32_t*>(&h);
}
__device__ __forceinline__ void ldsm4(uint32_t addr, uint32_t* r) {
    asm volatile("ldmatrix.sync.aligned.m8n8.x4.shared.b16 {%0,%1,%2,%3}, [%4];"
        : "=r"(r[0]), "=r"(r[1]), "=r"(r[2]), "=r"(r[3]) : "r"(addr));
}
__device__ __forceinline__ void ldsm4t(uint32_t addr, uint32_t* r) {
    asm volatile("ldmatrix.sync.aligned.m8n8.x4.trans.shared.b16 {%0,%1,%2,%3}, [%4];"
        : "=r"(r[0]), "=r"(r[1]), "=r"(r[2]), "=r"(r[3]) : "r"(addr));
}
__device__ __forceinline__ void mma_f16(float* c, const uint32_t* a, const uint32_t* b) {
    asm volatile(
        "mma.sync.aligned.m16n8k16.row.col.f32.f16.f16.f32 "
        "{%0,%1,%2,%3}, {%4,%5,%6,%7}, {%8,%9}, {%0,%1,%2,%3};"
        : "+f"(c[0]), "+f"(c[1]), "+f"(c[2]), "+f"(c[3])
        : "r"(a[0]), "r"(a[1]), "r"(a[2]), "r"(a[3]), "r"(b[0]), "r"(b[1]));
}

// ---------------------------------------------------------------------------
// FP16 GEMM: C[M,N] = A[M,K](half) @ W[K,N](half) + bias, half output.
// BM=128, BN=128, BK=32, 8 warps (warp tile 64x32), 2 CTAs/SM.
// 4-stage cp.async ring, interleaved LDSM prefetch, CORRECT waits:
// at iter s, committed groups cover stages 0..s+2; cp_wait<1> ->
// stages <= s+1 complete, covering phase-B's prefetch of stage s+1.
// ---------------------------------------------------------------------------
#define GM_ASTR 40                       // A smem row stride (halves)
#define GM_BSTR 136                      // B smem row stride (halves)
#define GM_AH   (128 * GM_ASTR)          // 5120 halves
#define GM_BH   (32 * GM_BSTR)           // 4352 halves
#define GM_STG  (GM_AH + GM_BH)          // 9472 halves / stage
#define GM_SMEM_BYTES (4 * GM_STG * 2)   // 75776 (x2 CTAs = 148 KB/SM)

template<bool QKV, bool GELU>
__global__ __launch_bounds__(256, 2)
void hgemm(int M, int N, int K,
           const __half* __restrict__ A,
           const __half* __restrict__ W0, const __half* __restrict__ W1_,
           const __half* __restrict__ W2_,
           __half* __restrict__ Ch0, __half* __restrict__ Ch1,
           __half* __restrict__ Ch2,
           int ldc,
           const float* __restrict__ bias0, const float* __restrict__ bias1,
           const float* __restrict__ bias2,
           const float* __restrict__ tau)
{
    extern __shared__ __half hsm[];

    const __half* W    = W0;
    __half*       Ch   = Ch0;
    const float*  bias = bias0;
    bool rope = false;
    float oscale = 1.0f;
    if (QKV) {
        int z = blockIdx.z;
        if (z == 1)      { W = W1_; Ch = Ch1; bias = bias1; }
        else if (z == 2) { W = W2_; Ch = Ch2; bias = bias2; }
        rope = (z < 2);
        if (z == 0) oscale = 0.125f;
    }

    const int tid  = threadIdx.x;
    const int lane = tid & 31;
    const int warp = tid >> 5;
    const int grp  = lane >> 2;
    const int tig  = lane & 3;
    const int wm0  = (warp >> 2) * 64;    // 0 or 64
    const int wn0  = (warp & 3) * 32;     // 0,32,64,96
    const int m0 = blockIdx.y * 128;
    const int n0 = blockIdx.x * 128;

    const uint32_t sbase = smem_u32(hsm);
    const uint32_t aOff = ((wm0 + (lane & 15)) * GM_ASTR + (lane >> 4) * 8) * 2;
    const int g8 = lane >> 3, r8 = lane & 7;
    const uint32_t bOff = (((g8 & 1) * 8 + r8) * GM_BSTR + wn0 + (g8 >> 1) * 8) * 2;

    float acc[4][4][4];
#pragma unroll
    for (int mi = 0; mi < 4; mi++)
#pragma unroll
        for (int ni = 0; ni < 4; ni++)
#pragma unroll
            for (int e = 0; e < 4; e++) acc[mi][ni][e] = 0.0f;

    auto load_stage = [&](int s) {
        uint32_t ab = sbase + (s & 3) * GM_STG * 2;
        uint32_t bb = ab + GM_AH * 2;
        int k0 = s * 32;
#pragma unroll
        for (int l = 0; l < 2; l++) {
            int c = tid + l * 256;
            int m = c >> 2, ch = c & 3;
            cp16(ab + (m * GM_ASTR + ch * 8) * 2,
                 A + (size_t)(m0 + m) * K + k0 + ch * 8);
        }
#pragma unroll
        for (int l = 0; l < 2; l++) {
            int c = tid + l * 256;
            int kk = c >> 4, nq = c & 15;
            cp16(bb + (kk * GM_BSTR + nq * 8) * 2,
                 W + (size_t)(k0 + kk) * N + n0 + nq * 8);
        }
        cp_commit();
    };

    // register fragment double-buffer
    uint32_t af[2][4][4], bf[2][4][2];

    auto load_frags = [&](int s, int kk, int p) {
        uint32_t ab = sbase + (s & 3) * GM_STG * 2;
        uint32_t bb = ab + GM_AH * 2;
#pragma unroll
        for (int mi = 0; mi < 4; mi++)
            ldsm4(ab + aOff + (mi * 16 * GM_ASTR + kk) * 2, af[p][mi]);
#pragma unroll
        for (int nip = 0; nip < 2; nip++)
            ldsm4t(bb + bOff + (kk * GM_BSTR + nip * 16) * 2, &bf[p][2 * nip][0]);
    };

    // 16 MMAs on buffer p; interleave the 6 LDSMs for (s_ld, kk_ld) -> buffer q.
    auto mma_block = [&](int p, int q, int s_ld, int kk_ld) {
        uint32_t ab = sbase + (s_ld & 3) * GM_STG * 2;
        uint32_t bb = ab + GM_AH * 2;
        mma_f16(acc[0][0], af[p][0], bf[p][0]);
        mma_f16(acc[0][1], af[p][0], bf[p][1]);
        ldsm4(ab + aOff + (0 * 16 * GM_ASTR + kk_ld) * 2, af[q][0]);
        mma_f16(acc[0][2], af[p][0], bf[p][2]);
        mma_f16(acc[0][3], af[p][0], bf[p][3]);
        ldsm4(ab + aOff + (1 * 16 * GM_ASTR + kk_ld) * 2, af[q][1]);
        mma_f16(acc[1][0], af[p][1], bf[p][0]);
        mma_f16(acc[1][1], af[p][1], bf[p][1]);
        ldsm4(ab + aOff + (2 * 16 * GM_ASTR + kk_ld) * 2, af[q][2]);
        mma_f16(acc[1][2], af[p][1], bf[p][2]);
        mma_f16(acc[1][3], af[p][1], bf[p][3]);
        ldsm4(ab + aOff + (3 * 16 * GM_ASTR + kk_ld) * 2, af[q][3]);
        mma_f16(acc[2][0], af[p][2], bf[p][0]);
        mma_f16(acc[2][1], af[p][2], bf[p][1]);
        ldsm4t(bb + bOff + (kk_ld * GM_BSTR + 0) * 2, &bf[q][0][0]);
        mma_f16(acc[2][2], af[p][2], bf[p][2]);
        mma_f16(acc[2][3], af[p][2], bf[p][3]);
        ldsm4t(bb + bOff + (kk_ld * GM_BSTR + 16) * 2, &bf[q][2][0]);
        mma_f16(acc[3][0], af[p][3], bf[p][0]);
        mma_f16(acc[3][1], af[p][3], bf[p][1]);
        mma_f16(acc[3][2], af[p][3], bf[p][2]);
        mma_f16(acc[3][3], af[p][3], bf[p][3]);
    };

    const int S = K / 32;
    load_stage(0); load_stage(1); load_stage(2);
    cp_wait<2>();          // stage 0 complete
    __syncthreads();
    load_frags(0, 0, 0);

    for (int s = 0; s < S; s++) {
        // committed groups so far: stages 0..min(s+2, S-1).
        // need stages <= s+1 complete (phase B prefetches stage s+1).
        if (s < S - 2) cp_wait<1>();
        else           cp_wait<0>();
        __syncthreads();              // visibility + ring-slot (s+3)%4 reuse
        if (s + 3 < S) load_stage(s + 3);
        mma_block(0, 1, s, 16);       // compute (s,0),  prefetch (s,16)
        mma_block(1, 0, s + 1, 0);    // compute (s,16), prefetch (s+1,0)
        // (s == S-1: phantom prefetch of stage S, never consumed)
    }

    // ---- epilogue (half output) ----
#pragma unroll
    for (int mi = 0; mi < 4; mi++) {
#pragma unroll
        for (int h = 0; h < 2; h++) {
            int row = m0 + wm0 + mi * 16 + grp + h * 8;
            float t = 0.0f;
            if (QKV) t = tau[row];
#pragma unroll
            for (int ni = 0; ni < 4; ni++) {
                int gcol = n0 + wn0 + ni * 8 + 2 * tig;
                float v0 = acc[mi][ni][h * 2 + 0];
                float v1 = acc[mi][ni][h * 2 + 1];
                if (bias) { v0 += bias[gcol]; v1 += bias[gcol + 1]; }
                if (GELU) {
                    v0 = 0.5f * v0 * (1.0f + erff(v0 * 0.7071067811865475f));
                    v1 = 0.5f * v1 * (1.0f + erff(v1 * 0.7071067811865475f));
                }
                if (QKV && rope) {
                    int j = (gcol & 63) >> 1;
                    float inv = __expf(-0.28782313662425572f * (float)j);
                    float sn, cs;
                    sincosf(t * inv, &sn, &cs);
                    float r0 = v0 * cs - v1 * sn;
                    float r1 = v1 * cs + v0 * sn;
                    v0 = r0 * oscale; v1 = r1 * oscale;
                }
                *(__half2*)(Ch + (size_t)row * ldc + gcol) =
                    __floats2half2_rn(v0, v1);
            }
        }
    }
}

// ---------------------------------------------------------------------------
// Fused float->half conversion of all 7 buffers in one launch.
// ---------------------------------------------------------------------------
struct F2HJob {
    const float4* in[7];
    __half2*      out[7];
    int           end[7];   // cumulative end offsets (in float4 units)
};

__global__ __launch_bounds__(256)
void f2h_all_kernel(F2HJob job)
{
    int i = blockIdx.x * 256 + threadIdx.x;
    int seg = 0, base = 0;
#pragma unroll
    for (int s = 0; s < 7; s++) {
        if (i >= job.end[s]) { seg = s + 1; base = job.end[s]; }
    }
    if (seg >= 7) return;
    int off = i - base;
    float4 v = job.in[seg][off];
    job.out[seg][2 * off]     = __floats2half2_rn(v.x, v.y);
    job.out[seg][2 * off + 1] = __floats2half2_rn(v.z, v.w);
}

// ---------------------------------------------------------------------------
// FP16 flash attention with ldmatrix + cp.async K/V double buffers.
// ---------------------------------------------------------------------------
#define FK_STR  72
#define FT_H    (128 * FK_STR)
#define FA_SMEM_BYTES (4 * FT_H * 2)      // 73728

__global__ __launch_bounds__(256)
void flash_kernel(const __half* __restrict__ q, const __half* __restrict__ k,
                  const __half* __restrict__ v, __half* __restrict__ ctx)
{
    extern __shared__ __half fsm[];
    const uint32_t sbase = smem_u32(fsm);

    const int tid  = threadIdx.x;
    const int lane = tid & 31;
    const int warp = tid >> 5;
    const int grp  = lane >> 2;
    const int tig  = lane & 3;
    const int g8 = lane >> 3, r8 = lane & 7;

    const int m0 = blockIdx.x * 128;
    const int bh = blockIdx.y;
    const int b  = bh >> 4;
    const int h  = bh & 15;

    const __half* qb = q + ((size_t)b * SEQ) * DMODEL + h * HEADDIM;
    const __half* kb = k + ((size_t)b * SEQ) * DMODEL + h * HEADDIM;
    const __half* vb = v + ((size_t)b * SEQ) * DMODEL + h * HEADDIM;

    const uint32_t qOff = ((warp * 16 + (lane & 15)) * FK_STR + (lane >> 4) * 8) * 2;
    const uint32_t kOff = ((r8 + (g8 >> 1) * 8) * FK_STR + (g8 & 1) * 8) * 2;
    const uint32_t vOff = ((r8 + (g8 & 1) * 8) * FK_STR + (g8 >> 1) * 8) * 2;

#pragma unroll
    for (int l = 0; l < 4; l++) {
        int c = tid + l * 256;
        int r = c >> 3, ch = c & 7;
        cp16(sbase + (r * FK_STR + ch * 8) * 2,
             qb + (size_t)(m0 + r) * DMODEL + ch * 8);
    }
    cp_commit(); cp_wait<0>(); __syncthreads();

    uint32_t aq[4][4];
#pragma unroll
    for (int kc = 0; kc < 4; kc++)
        ldsm4(sbase + qOff + kc * 32, aq[kc]);
    __syncthreads();

    float o[8][4];
#pragma unroll
    for (int ni = 0; ni < 8; ni++)
#pragma unroll
        for (int e = 0; e < 4; e++) o[ni][e] = 0.0f;
    float mrun0 = -1e30f, mrun1 = -1e30f, lrun0 = 0.0f, lrun1 = 0.0f;

    auto load_kv = [&](int t) {
        uint32_t kd = sbase + (t & 1) * FT_H * 2;
        uint32_t vd = sbase + (2 + (t & 1)) * FT_H * 2;
#pragma unroll
        for (int l = 0; l < 4; l++) {
            int c = tid + l * 256;
            int r = c >> 3, ch = c & 7;
            uint32_t so = (r * FK_STR + ch * 8) * 2;
            size_t  go = (size_t)(t * 128 + r) * DMODEL + ch * 8;
            cp16(kd + so, kb + go);
            cp16(vd + so, vb + go);
        }
        cp_commit();
    };

    load_kv(0);

    const int NTILE = SEQ / 128;
    for (int t = 0; t < NTILE; t++) {
        cp_wait<0>();
        __syncthreads();
        if (t + 1 < NTILE) load_kv(t + 1);

        uint32_t kbuf = sbase + (t & 1) * FT_H * 2;
        uint32_t vbuf = sbase + (2 + (t & 1)) * FT_H * 2;

        float sacc[16][4];
#pragma unroll
        for (int ni = 0; ni < 16; ni++)
#pragma unroll
            for (int e = 0; e < 4; e++) sacc[ni][e] = 0.0f;

        // ---- S = Q @ K^T, pipelined ----
        {
            uint32_t bf2[2][4];
            ldsm4(kbuf + kOff, bf2[0]);
#pragma unroll
            for (int it = 0; it < 32; it++) {
                if (it + 1 < 32) {
                    int kc2 = (it + 1) >> 3, nip2 = (it + 1) & 7;
                    ldsm4(kbuf + kOff + (nip2 * 16 * FK_STR + kc2 * 16) * 2,
                          bf2[(it + 1) & 1]);
                }
                int kc = it >> 3, nip = it & 7;
                mma_f16(sacc[2 * nip    ], aq[kc], &bf2[it & 1][0]);
                mma_f16(sacc[2 * nip + 1], aq[kc], &bf2[it & 1][2]);
            }
        }

        float tmax0 = -1e30f, tmax1 = -1e30f;
#pragma unroll
        for (int ni = 0; ni < 16; ni++) {
            tmax0 = fmaxf(tmax0, fmaxf(sacc[ni][0], sacc[ni][1]));
            tmax1 = fmaxf(tmax1, fmaxf(sacc[ni][2], sacc[ni][3]));
        }
        tmax0 = fmaxf(tmax0, __shfl_xor_sync(0xffffffffu, tmax0, 1));
        tmax0 = fmaxf(tmax0, __shfl_xor_sync(0xffffffffu, tmax0, 2));
        tmax1 = fmaxf(tmax1, __shfl_xor_sync(0xffffffffu, tmax1, 1));
        tmax1 = fmaxf(tmax1, __shfl_xor_sync(0xffffffffu, tmax1, 2));

        float nm0 = fmaxf(mrun0, tmax0);
        float nm1 = fmaxf(mrun1, tmax1);
        float sc0 = __expf(mrun0 - nm0);
        float sc1 = __expf(mrun1 - nm1);
        mrun0 = nm0; mrun1 = nm1;

        float sum0 = 0.0f, sum1 = 0.0f;
#pragma unroll
        for (int ni = 0; ni < 16; ni++) {
            sacc[ni][0] = __expf(sacc[ni][0] - nm0);
            sacc[ni][1] = __expf(sacc[ni][1] - nm0);
            sacc[ni][2] = __expf(sacc[ni][2] - nm1);
            sacc[ni][3] = __expf(sacc[ni][3] - nm1);
            sum0 += sacc[ni][0] + sacc[ni][1];
            sum1 += sacc[ni][2] + sacc[ni][3];
        }
        sum0 += __shfl_xor_sync(0xffffffffu, sum0, 1);
        sum0 += __shfl_xor_sync(0xffffffffu, sum0, 2);
        sum1 += __shfl_xor_sync(0xffffffffu, sum1, 1);
        sum1 += __shfl_xor_sync(0xffffffffu, sum1, 2);
        lrun0 = lrun0 * sc0 + sum0;
        lrun1 = lrun1 * sc1 + sum1;

#pragma unroll
        for (int ni = 0; ni < 8; ni++) {
            o[ni][0] *= sc0; o[ni][1] *= sc0;
            o[ni][2] *= sc1; o[ni][3] *= sc1;
        }

        uint32_t pA[8][4];
#pragma unroll
        for (int kc = 0; kc < 8; kc++) {
            pA[kc][0] = pack2(sacc[2 * kc    ][0], sacc[2 * kc    ][1]);
            pA[kc][1] = pack2(sacc[2 * kc    ][2], sacc[2 * kc    ][3]);
            pA[kc][2] = pack2(sacc[2 * kc + 1][0], sacc[2 * kc + 1][1]);
            pA[kc][3] = pack2(sacc[2 * kc + 1][2], sacc[2 * kc + 1][3]);
        }

        // ---- O += P @ V, pipelined ----
        {
            uint32_t bb2[2][4];
            ldsm4t(vbuf + vOff, bb2[0]);
#pragma unroll
            for (int it = 0; it < 32; it++) {
                if (it + 1 < 32) {
                    int kc2 = (it + 1) >> 2, nip2 = (it + 1) & 3;
                    ldsm4t(vbuf + vOff + (kc2 * 16 * FK_STR + nip2 * 16) * 2,
                           bb2[(it + 1) & 1]);
                }
                int kc = it >> 2, nip = it & 3;
                mma_f16(o[2 * nip    ], pA[kc], &bb2[it & 1][0]);
                mma_f16(o[2 * nip + 1], pA[kc], &bb2[it & 1][2]);
            }
        }
    }

    float inv0 = 1.0f / lrun0;
    float inv1 = 1.0f / lrun1;
    int r0 = m0 + warp * 16 + grp;
    __half* cb = ctx + ((size_t)b * SEQ) * DMODEL + h * HEADDIM;
#pragma unroll
    for (int ni = 0; ni < 8; ni++) {
        int col = ni * 8 + 2 * tig;
        *(__half2*)(cb + (size_t)(r0    ) * DMODEL + col) =
            __floats2half2_rn(o[ni][0] * inv0, o[ni][1] * inv0);
        *(__half2*)(cb + (size_t)(r0 + 8) * DMODEL + col) =
            __floats2half2_rn(o[ni][2] * inv1, o[ni][3] * inv1);
    }
}

// ---------------------------------------------------------------------------
// Fused residual + LayerNorm: out = LN(a + b) * g + be.
// a is fp32 (residual), b is half (GEMM branch output).
// ---------------------------------------------------------------------------
__global__ __launch_bounds__(256)
void ln_kernel(const float* __restrict__ a, const __half* __restrict__ b,
               const float* __restrict__ g, const float* __restrict__ be,
               float* __restrict__ out, __half* __restrict__ outh)
{
    const int D = DMODEL;
    size_t row = blockIdx.x;
    const float*  pa = a + row * D;
    const __half* pb = b + row * D;
    int tid = threadIdx.x;
    __shared__ float red[256];

    float x[4];
    float s = 0.0f;
#pragma unroll
    for (int i = 0; i < 4; i++) {
        int c = tid + i * 256;
        x[i] = pa[c] + __half2float(pb[c]);
        s += x[i];
    }
    red[tid] = s;
    __syncthreads();
    for (int t = 128; t > 0; t >>= 1) {
        if (tid < t) red[tid] += red[tid + t];
        __syncthreads();
    }
    float mu = red[0] * (1.0f / D);
    __syncthreads();

    float v = 0.0f;
#pragma unroll
    for (int i = 0; i < 4; i++) {
        float d = x[i] - mu;
        v += d * d;
    }
    red[tid] = v;
    __syncthreads();
    for (int t = 128; t > 0; t >>= 1) {
        if (tid < t) red[tid] += red[tid + t];
        __syncthreads();
    }
    float var = red[0] * (1.0f / D);
    float r = rsqrtf(var + 1e-5f);
#pragma unroll
    for (int i = 0; i < 4; i++) {
        int c = tid + i * 256;
        float y = (x[i] - mu) * r * g[c] + be[c];
        out[row * D + c] = y;
        if (outh) outh[row * D + c] = __float2half_rn(y);
    }
}

// ---------------------------------------------------------------------------
// Host-side launch
// ---------------------------------------------------------------------------
static void* symptr_v(const void* sym)
{
    void* p = nullptr;
    cudaGetSymbolAddress(&p, sym);
    return p;
}

extern "C" void kernel_launch(void* const* d_in, const int* in_sizes, int n_in,
                              void* d_out, int out_size)
{
    const float* src = (const float*)d_in[0];
    const float* tau = (const float*)d_in[1];
    const float* Wq  = (const float*)d_in[2];
    const float* bq  = (const float*)d_in[3];
    const float* Wk  = (const float*)d_in[4];
    const float* bk  = (const float*)d_in[5];
    const float* Wv  = (const float*)d_in[6];
    const float* bv  = (const float*)d_in[7];
    const float* Wo  = (const float*)d_in[8];
    const float* bo  = (const float*)d_in[9];
    const float* W1  = (const float*)d_in[10];
    const float* b1  = (const float*)d_in[11];
    const float* W2  = (const float*)d_in[12];
    const float* b2  = (const float*)d_in[13];
    const float* g1  = (const float*)d_in[14];
    const float* be1 = (const float*)d_in[15];
    const float* g2  = (const float*)d_in[16];
    const float* be2 = (const float*)d_in[17];
    float* out = (float*)d_out;

    __half* srch = (__half*)symptr_v(g_srch);
    __half* qh   = (__half*)symptr_v(g_qh);
    __half* kh   = (__half*)symptr_v(g_kh);
    __half* vh   = (__half*)symptr_v(g_vh);
    __half* ctxh = (__half*)symptr_v(g_ctxh);
    __half* h1h  = (__half*)symptr_v(g_h1h);
    __half* f1h  = (__half*)symptr_v(g_f1h);
    __half* aoh  = (__half*)symptr_v(g_aoh);
    __half* f2h  = (__half*)symptr_v(g_f2h2);
    float*  h1f  = (float*)symptr_v(g_h1f);
    __half* wqH  = (__half*)symptr_v(g_wqH);
    __half* wkH  = (__half*)symptr_v(g_wkH);
    __half* wvH  = (__half*)symptr_v(g_wvH);
    __half* woH  = (__half*)symptr_v(g_woH);
    __half* w1H  = (__half*)symptr_v(g_w1H);
    __half* w2H  = (__half*)symptr_v(g_w2H);

    cudaFuncSetAttribute(flash_kernel,
                         cudaFuncAttributeMaxDynamicSharedMemorySize, FA_SMEM_BYTES);
    cudaFuncSetAttribute(hgemm<true,  false>,
                         cudaFuncAttributeMaxDynamicSharedMemorySize, GM_SMEM_BYTES);
    cudaFuncSetAttribute(hgemm<false, false>,
                         cudaFuncAttributeMaxDynamicSharedMemorySize, GM_SMEM_BYTES);
    cudaFuncSetAttribute(hgemm<false, true>,
                         cudaFuncAttributeMaxDynamicSharedMemorySize, GM_SMEM_BYTES);

    // ---- prep: single fused f2h of all weights + src ----
    {
        const int nW = DMODEL * DMODEL / 4;        // 262144
        const int nF = DMODEL * DFF / 4;           // 1048576
        const int nS = TOKENS * DMODEL / 4;        // 1048576
        F2HJob job;
        job.in[0] = (const float4*)Wq;  job.out[0] = (__half2*)wqH;
        job.in[1] = (const float4*)Wk;  job.out[1] = (__half2*)wkH;
        job.in[2] = (const float4*)Wv;  job.out[2] = (__half2*)wvH;
        job.in[3] = (const float4*)Wo;  job.out[3] = (__half2*)woH;
        job.in[4] = (const float4*)W1;  job.out[4] = (__half2*)w1H;
        job.in[5] = (const float4*)W2;  job.out[5] = (__half2*)w2H;
        job.in[6] = (const float4*)src; job.out[6] = (__half2*)srch;
        int acc = 0;
        int sizes[7] = { nW, nW, nW, nW, nF, nF, nS };
        for (int s = 0; s < 7; s++) { acc += sizes[s]; job.end[s] = acc; }
        f2h_all_kernel<<<(acc + 255) / 256, 256>>>(job);
    }

    // ---- QKV (+RoPE, q pre-scaled) ----
    hgemm<true, false>
        <<<dim3(DMODEL / 128, TOKENS / 128, 3), 256, GM_SMEM_BYTES>>>(
        TOKENS, DMODEL, DMODEL, srch, wqH, wkH, wvH,
        qh, kh, vh, DMODEL, bq, bk, bv, tau);

    // ---- flash attention -> ctx (half) ----
    flash_kernel<<<dim3(SEQ / 128, BATCH * NHEADS), 256, FA_SMEM_BYTES>>>(
        qh, kh, vh, ctxh);

    // ---- output projection -> aoh (half) ----
    hgemm<false, false>
        <<<dim3(DMODEL / 128, TOKENS / 128, 1), 256, GM_SMEM_BYTES>>>(
        TOKENS, DMODEL, DMODEL, ctxh, woH, nullptr, nullptr,
        aoh, nullptr, nullptr, DMODEL, bo, nullptr, nullptr, nullptr);

    // ---- LN1 -> h1 (fp32 + half) ----
    ln_kernel<<<TOKENS, 256>>>(src, aoh, g1, be1, h1f, h1h);

    // ---- FFN1 (GELU) -> f1 (half) ----
    hgemm<false, true>
        <<<dim3(DFF / 128, TOKENS / 128, 1), 256, GM_SMEM_BYTES>>>(
        TOKENS, DFF, DMODEL, h1h, w1H, nullptr, nullptr,
        f1h, nullptr, nullptr, DFF, b1, nullptr, nullptr, nullptr);

    // ---- FFN2 -> f2 (half) ----
    hgemm<false, false>
        <<<dim3(DMODEL / 128, TOKENS / 128, 1), 256, GM_SMEM_BYTES>>>(
        TOKENS, DMODEL, DFF, f1h, w2H, nullptr, nullptr,
        f2h, nullptr, nullptr, DMODEL, b2, nullptr, nullptr, nullptr);

    // ---- LN2 -> out ----
    ln_kernel<<<TOKENS, 256>>>(h1f, f2h, g2, be2, out, nullptr);

    (void)in_sizes; (void)n_in; (void)out_size;
}

// round 16
// speedup vs baseline: 1.1926x; 1.0041x over previous
#include <cuda_runtime.h>
#include <cuda_fp16.h>
#include <math.h>
#include <cstdint>

// ---------------------------------------------------------------------------
// Problem constants
// ---------------------------------------------------------------------------
#define BATCH   2
#define SEQ     2048
#define DMODEL  1024
#define NHEADS  16
#define HEADDIM 64
#define DFF     4096
#define TOKENS  (BATCH * SEQ)          // 4096

// ---------------------------------------------------------------------------
// Scratch (static device allocations)
// ---------------------------------------------------------------------------
__device__ __half g_srch[TOKENS * DMODEL];
__device__ __half g_qh  [TOKENS * DMODEL];
__device__ __half g_kh  [TOKENS * DMODEL];
__device__ __half g_vh  [TOKENS * DMODEL];
__device__ __half g_ctxh[TOKENS * DMODEL];
__device__ __half g_h1h [TOKENS * DMODEL];
__device__ __half g_f1h [(size_t)TOKENS * DFF];
__device__ __half g_aoh [TOKENS * DMODEL];
__device__ __half g_f2h2[TOKENS * DMODEL];
// half weights, natural [K][N] layout
__device__ __half g_wqH[DMODEL * DMODEL];
__device__ __half g_wkH[DMODEL * DMODEL];
__device__ __half g_wvH[DMODEL * DMODEL];
__device__ __half g_woH[DMODEL * DMODEL];
__device__ __half g_w1H[(size_t)DMODEL * DFF];
__device__ __half g_w2H[(size_t)DFF * DMODEL];

// ---------------------------------------------------------------------------
// PTX helpers
// ---------------------------------------------------------------------------
__device__ __forceinline__ uint32_t smem_u32(const void* p) {
    return (uint32_t)__cvta_generic_to_shared(p);
}
__device__ __forceinline__ void cp16(uint32_t s, const void* g) {
    asm volatile("cp.async.cg.shared.global [%0], [%1], 16;" :: "r"(s), "l"(g));
}
__device__ __forceinline__ void cp_commit() {
    asm volatile("cp.async.commit_group;");
}
template<int N>
__device__ __forceinline__ void cp_wait() {
    asm volatile("cp.async.wait_group %0;" :: "n"(N));
}
__device__ __forceinline__ uint32_t pack2(float lo, float hi) {
    __half2 h = __floats2half2_rn(lo, hi);
    return *reinterpret_cast<uint32_t*>(&h);
}
__device__ __forceinline__ void ldsm4(uint32_t addr, uint32_t* r) {
    asm volatile("ldmatrix.sync.aligned.m8n8.x4.shared.b16 {%0,%1,%2,%3}, [%4];"
        : "=r"(r[0]), "=r"(r[1]), "=r"(r[2]), "=r"(r[3]) : "r"(addr));
}
__device__ __forceinline__ void ldsm4t(uint32_t addr, uint32_t* r) {
    asm volatile("ldmatrix.sync.aligned.m8n8.x4.trans.shared.b16 {%0,%1,%2,%3}, [%4];"
        : "=r"(r[0]), "=r"(r[1]), "=r"(r[2]), "=r"(r[3]) : "r"(addr));
}
__device__ __forceinline__ void mma_f16(float* c, const uint32_t* a, const uint32_t* b) {
    asm volatile(
        "mma.sync.aligned.m16n8k16.row.col.f32.f16.f16.f32 "
        "{%0,%1,%2,%3}, {%4,%5,%6,%7}, {%8,%9}, {%0,%1,%2,%3};"
        : "+f"(c[0]), "+f"(c[1]), "+f"(c[2]), "+f"(c[3])
        : "r"(a[0]), "r"(a[1]), "r"(a[2]), "r"(a[3]), "r"(b[0]), "r"(b[1]));
}

// ---------------------------------------------------------------------------
// FP16 GEMM: C[M,N] = A[M,K](half) @ W[K,N](half) + bias, half output.
// BM=128, BN=128, BK=32, 8 warps (warp tile 64x32), 2 CTAs/SM.
// 4-stage cp.async ring, interleaved LDSM prefetch, correct waits.
// (unchanged from R15 — the verified best GEMM config)
// ---------------------------------------------------------------------------
#define GM_ASTR 40                       // A smem row stride (halves)
#define GM_BSTR 136                      // B smem row stride (halves)
#define GM_AH   (128 * GM_ASTR)          // 5120 halves
#define GM_BH   (32 * GM_BSTR)           // 4352 halves
#define GM_STG  (GM_AH + GM_BH)          // 9472 halves / stage
#define GM_SMEM_BYTES (4 * GM_STG * 2)   // 75776 (x2 CTAs = 148 KB/SM)

template<bool QKV, bool GELU>
__global__ __launch_bounds__(256, 2)
void hgemm(int M, int N, int K,
           const __half* __restrict__ A,
           const __half* __restrict__ W0, const __half* __restrict__ W1_,
           const __half* __restrict__ W2_,
           __half* __restrict__ Ch0, __half* __restrict__ Ch1,
           __half* __restrict__ Ch2,
           int ldc,
           const float* __restrict__ bias0, const float* __restrict__ bias1,
           const float* __restrict__ bias2,
           const float* __restrict__ tau)
{
    extern __shared__ __half hsm[];

    const __half* W    = W0;
    __half*       Ch   = Ch0;
    const float*  bias = bias0;
    bool rope = false;
    float oscale = 1.0f;
    if (QKV) {
        int z = blockIdx.z;
        if (z == 1)      { W = W1_; Ch = Ch1; bias = bias1; }
        else if (z == 2) { W = W2_; Ch = Ch2; bias = bias2; }
        rope = (z < 2);
        if (z == 0) oscale = 0.125f;
    }

    const int tid  = threadIdx.x;
    const int lane = tid & 31;
    const int warp = tid >> 5;
    const int grp  = lane >> 2;
    const int tig  = lane & 3;
    const int wm0  = (warp >> 2) * 64;    // 0 or 64
    const int wn0  = (warp & 3) * 32;     // 0,32,64,96
    const int m0 = blockIdx.y * 128;
    const int n0 = blockIdx.x * 128;

    const uint32_t sbase = smem_u32(hsm);
    const uint32_t aOff = ((wm0 + (lane & 15)) * GM_ASTR + (lane >> 4) * 8) * 2;
    const int g8 = lane >> 3, r8 = lane & 7;
    const uint32_t bOff = (((g8 & 1) * 8 + r8) * GM_BSTR + wn0 + (g8 >> 1) * 8) * 2;

    float acc[4][4][4];
#pragma unroll
    for (int mi = 0; mi < 4; mi++)
#pragma unroll
        for (int ni = 0; ni < 4; ni++)
#pragma unroll
            for (int e = 0; e < 4; e++) acc[mi][ni][e] = 0.0f;

    auto load_stage = [&](int s) {
        uint32_t ab = sbase + (s & 3) * GM_STG * 2;
        uint32_t bb = ab + GM_AH * 2;
        int k0 = s * 32;
#pragma unroll
        for (int l = 0; l < 2; l++) {
            int c = tid + l * 256;
            int m = c >> 2, ch = c & 3;
            cp16(ab + (m * GM_ASTR + ch * 8) * 2,
                 A + (size_t)(m0 + m) * K + k0 + ch * 8);
        }
#pragma unroll
        for (int l = 0; l < 2; l++) {
            int c = tid + l * 256;
            int kk = c >> 4, nq = c & 15;
            cp16(bb + (kk * GM_BSTR + nq * 8) * 2,
                 W + (size_t)(k0 + kk) * N + n0 + nq * 8);
        }
        cp_commit();
    };

    // register fragment double-buffer
    uint32_t af[2][4][4], bf[2][4][2];

    auto load_frags = [&](int s, int kk, int p) {
        uint32_t ab = sbase + (s & 3) * GM_STG * 2;
        uint32_t bb = ab + GM_AH * 2;
#pragma unroll
        for (int mi = 0; mi < 4; mi++)
            ldsm4(ab + aOff + (mi * 16 * GM_ASTR + kk) * 2, af[p][mi]);
#pragma unroll
        for (int nip = 0; nip < 2; nip++)
            ldsm4t(bb + bOff + (kk * GM_BSTR + nip * 16) * 2, &bf[p][2 * nip][0]);
    };

    // 16 MMAs on buffer p; interleave the 6 LDSMs for (s_ld, kk_ld) -> buffer q.
    auto mma_block = [&](int p, int q, int s_ld, int kk_ld) {
        uint32_t ab = sbase + (s_ld & 3) * GM_STG * 2;
        uint32_t bb = ab + GM_AH * 2;
        mma_f16(acc[0][0], af[p][0], bf[p][0]);
        mma_f16(acc[0][1], af[p][0], bf[p][1]);
        ldsm4(ab + aOff + (0 * 16 * GM_ASTR + kk_ld) * 2, af[q][0]);
        mma_f16(acc[0][2], af[p][0], bf[p][2]);
        mma_f16(acc[0][3], af[p][0], bf[p][3]);
        ldsm4(ab + aOff + (1 * 16 * GM_ASTR + kk_ld) * 2, af[q][1]);
        mma_f16(acc[1][0], af[p][1], bf[p][0]);
        mma_f16(acc[1][1], af[p][1], bf[p][1]);
        ldsm4(ab + aOff + (2 * 16 * GM_ASTR + kk_ld) * 2, af[q][2]);
        mma_f16(acc[1][2], af[p][1], bf[p][2]);
        mma_f16(acc[1][3], af[p][1], bf[p][3]);
        ldsm4(ab + aOff + (3 * 16 * GM_ASTR + kk_ld) * 2, af[q][3]);
        mma_f16(acc[2][0], af[p][2], bf[p][0]);
        mma_f16(acc[2][1], af[p][2], bf[p][1]);
        ldsm4t(bb + bOff + (kk_ld * GM_BSTR + 0) * 2, &bf[q][0][0]);
        mma_f16(acc[2][2], af[p][2], bf[p][2]);
        mma_f16(acc[2][3], af[p][2], bf[p][3]);
        ldsm4t(bb + bOff + (kk_ld * GM_BSTR + 16) * 2, &bf[q][2][0]);
        mma_f16(acc[3][0], af[p][3], bf[p][0]);
        mma_f16(acc[3][1], af[p][3], bf[p][1]);
        mma_f16(acc[3][2], af[p][3], bf[p][2]);
        mma_f16(acc[3][3], af[p][3], bf[p][3]);
    };

    const int S = K / 32;
    load_stage(0); load_stage(1); load_stage(2);
    cp_wait<2>();          // stage 0 complete
    __syncthreads();
    load_frags(0, 0, 0);

    for (int s = 0; s < S; s++) {
        // committed groups so far: stages 0..min(s+2, S-1).
        // need stages <= s+1 complete (phase B prefetches stage s+1).
        if (s < S - 2) cp_wait<1>();
        else           cp_wait<0>();
        __syncthreads();              // visibility + ring-slot (s+3)%4 reuse
        if (s + 3 < S) load_stage(s + 3);
        mma_block(0, 1, s, 16);       // compute (s,0),  prefetch (s,16)
        mma_block(1, 0, s + 1, 0);    // compute (s,16), prefetch (s+1,0)
        // (s == S-1: phantom prefetch of stage S, never consumed)
    }

    // ---- epilogue (half output) ----
#pragma unroll
    for (int mi = 0; mi < 4; mi++) {
#pragma unroll
        for (int h = 0; h < 2; h++) {
            int row = m0 + wm0 + mi * 16 + grp + h * 8;
            float t = 0.0f;
            if (QKV) t = tau[row];
#pragma unroll
            for (int ni = 0; ni < 4; ni++) {
                int gcol = n0 + wn0 + ni * 8 + 2 * tig;
                float v0 = acc[mi][ni][h * 2 + 0];
                float v1 = acc[mi][ni][h * 2 + 1];
                if (bias) { v0 += bias[gcol]; v1 += bias[gcol + 1]; }
                if (GELU) {
                    v0 = 0.5f * v0 * (1.0f + erff(v0 * 0.7071067811865475f));
                    v1 = 0.5f * v1 * (1.0f + erff(v1 * 0.7071067811865475f));
                }
                if (QKV && rope) {
                    int j = (gcol & 63) >> 1;
                    float inv = __expf(-0.28782313662425572f * (float)j);
                    float sn, cs;
                    sincosf(t * inv, &sn, &cs);
                    float r0 = v0 * cs - v1 * sn;
                    float r1 = v1 * cs + v0 * sn;
                    v0 = r0 * oscale; v1 = r1 * oscale;
                }
                *(__half2*)(Ch + (size_t)row * ldc + gcol) =
                    __floats2half2_rn(v0, v1);
            }
        }
    }
}

// ---------------------------------------------------------------------------
// Fused float->half conversion of all 7 buffers in one launch.
// ---------------------------------------------------------------------------
struct F2HJob {
    const float4* in[7];
    __half2*      out[7];
    int           end[7];   // cumulative end offsets (in float4 units)
};

__global__ __launch_bounds__(256)
void f2h_all_kernel(F2HJob job)
{
    int i = blockIdx.x * 256 + threadIdx.x;
    int seg = 0, base = 0;
#pragma unroll
    for (int s = 0; s < 7; s++) {
        if (i >= job.end[s]) { seg = s + 1; base = job.end[s]; }
    }
    if (seg >= 7) return;
    int off = i - base;
    float4 v = job.in[seg][off];
    job.out[seg][2 * off]     = __floats2half2_rn(v.x, v.y);
    job.out[seg][2 * off + 1] = __floats2half2_rn(v.z, v.w);
}

// ---------------------------------------------------------------------------
// FP16 flash attention with ldmatrix + cp.async K/V double buffers.
// ---------------------------------------------------------------------------
#define FK_STR  72
#define FT_H    (128 * FK_STR)
#define FA_SMEM_BYTES (4 * FT_H * 2)      // 73728

__global__ __launch_bounds__(256)
void flash_kernel(const __half* __restrict__ q, const __half* __restrict__ k,
                  const __half* __restrict__ v, __half* __restrict__ ctx)
{
    extern __shared__ __half fsm[];
    const uint32_t sbase = smem_u32(fsm);

    const int tid  = threadIdx.x;
    const int lane = tid & 31;
    const int warp = tid >> 5;
    const int grp  = lane >> 2;
    const int tig  = lane & 3;
    const int g8 = lane >> 3, r8 = lane & 7;

    const int m0 = blockIdx.x * 128;
    const int bh = blockIdx.y;
    const int b  = bh >> 4;
    const int h  = bh & 15;

    const __half* qb = q + ((size_t)b * SEQ) * DMODEL + h * HEADDIM;
    const __half* kb = k + ((size_t)b * SEQ) * DMODEL + h * HEADDIM;
    const __half* vb = v + ((size_t)b * SEQ) * DMODEL + h * HEADDIM;

    const uint32_t qOff = ((warp * 16 + (lane & 15)) * FK_STR + (lane >> 4) * 8) * 2;
    const uint32_t kOff = ((r8 + (g8 >> 1) * 8) * FK_STR + (g8 & 1) * 8) * 2;
    const uint32_t vOff = ((r8 + (g8 & 1) * 8) * FK_STR + (g8 >> 1) * 8) * 2;

#pragma unroll
    for (int l = 0; l < 4; l++) {
        int c = tid + l * 256;
        int r = c >> 3, ch = c & 7;
        cp16(sbase + (r * FK_STR + ch * 8) * 2,
             qb + (size_t)(m0 + r) * DMODEL + ch * 8);
    }
    cp_commit(); cp_wait<0>(); __syncthreads();

    uint32_t aq[4][4];
#pragma unroll
    for (int kc = 0; kc < 4; kc++)
        ldsm4(sbase + qOff + kc * 32, aq[kc]);
    __syncthreads();

    float o[8][4];
#pragma unroll
    for (int ni = 0; ni < 8; ni++)
#pragma unroll
        for (int e = 0; e < 4; e++) o[ni][e] = 0.0f;
    float mrun0 = -1e30f, mrun1 = -1e30f, lrun0 = 0.0f, lrun1 = 0.0f;

    auto load_kv = [&](int t) {
        uint32_t kd = sbase + (t & 1) * FT_H * 2;
        uint32_t vd = sbase + (2 + (t & 1)) * FT_H * 2;
#pragma unroll
        for (int l = 0; l < 4; l++) {
            int c = tid + l * 256;
            int r = c >> 3, ch = c & 7;
            uint32_t so = (r * FK_STR + ch * 8) * 2;
            size_t  go = (size_t)(t * 128 + r) * DMODEL + ch * 8;
            cp16(kd + so, kb + go);
            cp16(vd + so, vb + go);
        }
        cp_commit();
    };

    load_kv(0);

    const int NTILE = SEQ / 128;
    for (int t = 0; t < NTILE; t++) {
        cp_wait<0>();
        __syncthreads();
        if (t + 1 < NTILE) load_kv(t + 1);

        uint32_t kbuf = sbase + (t & 1) * FT_H * 2;
        uint32_t vbuf = sbase + (2 + (t & 1)) * FT_H * 2;

        float sacc[16][4];
#pragma unroll
        for (int ni = 0; ni < 16; ni++)
#pragma unroll
            for (int e = 0; e < 4; e++) sacc[ni][e] = 0.0f;

        // ---- S = Q @ K^T, pipelined ----
        {
            uint32_t bf2[2][4];
            ldsm4(kbuf + kOff, bf2[0]);
#pragma unroll
            for (int it = 0; it < 32; it++) {
                if (it + 1 < 32) {
                    int kc2 = (it + 1) >> 3, nip2 = (it + 1) & 7;
                    ldsm4(kbuf + kOff + (nip2 * 16 * FK_STR + kc2 * 16) * 2,
                          bf2[(it + 1) & 1]);
                }
                int kc = it >> 3, nip = it & 7;
                mma_f16(sacc[2 * nip    ], aq[kc], &bf2[it & 1][0]);
                mma_f16(sacc[2 * nip + 1], aq[kc], &bf2[it & 1][2]);
            }
        }

        float tmax0 = -1e30f, tmax1 = -1e30f;
#pragma unroll
        for (int ni = 0; ni < 16; ni++) {
            tmax0 = fmaxf(tmax0, fmaxf(sacc[ni][0], sacc[ni][1]));
            tmax1 = fmaxf(tmax1, fmaxf(sacc[ni][2], sacc[ni][3]));
        }
        tmax0 = fmaxf(tmax0, __shfl_xor_sync(0xffffffffu, tmax0, 1));
        tmax0 = fmaxf(tmax0, __shfl_xor_sync(0xffffffffu, tmax0, 2));
        tmax1 = fmaxf(tmax1, __shfl_xor_sync(0xffffffffu, tmax1, 1));
        tmax1 = fmaxf(tmax1, __shfl_xor_sync(0xffffffffu, tmax1, 2));

        float nm0 = fmaxf(mrun0, tmax0);
        float nm1 = fmaxf(mrun1, tmax1);
        float sc0 = __expf(mrun0 - nm0);
        float sc1 = __expf(mrun1 - nm1);
        mrun0 = nm0; mrun1 = nm1;

        float sum0 = 0.0f, sum1 = 0.0f;
#pragma unroll
        for (int ni = 0; ni < 16; ni++) {
            sacc[ni][0] = __expf(sacc[ni][0] - nm0);
            sacc[ni][1] = __expf(sacc[ni][1] - nm0);
            sacc[ni][2] = __expf(sacc[ni][2] - nm1);
            sacc[ni][3] = __expf(sacc[ni][3] - nm1);
            sum0 += sacc[ni][0] + sacc[ni][1];
            sum1 += sacc[ni][2] + sacc[ni][3];
        }
        sum0 += __shfl_xor_sync(0xffffffffu, sum0, 1);
        sum0 += __shfl_xor_sync(0xffffffffu, sum0, 2);
        sum1 += __shfl_xor_sync(0xffffffffu, sum1, 1);
        sum1 += __shfl_xor_sync(0xffffffffu, sum1, 2);
        lrun0 = lrun0 * sc0 + sum0;
        lrun1 = lrun1 * sc1 + sum1;

#pragma unroll
        for (int ni = 0; ni < 8; ni++) {
            o[ni][0] *= sc0; o[ni][1] *= sc0;
            o[ni][2] *= sc1; o[ni][3] *= sc1;
        }

        uint32_t pA[8][4];
#pragma unroll
        for (int kc = 0; kc < 8; kc++) {
            pA[kc][0] = pack2(sacc[2 * kc    ][0], sacc[2 * kc    ][1]);
            pA[kc][1] = pack2(sacc[2 * kc    ][2], sacc[2 * kc    ][3]);
            pA[kc][2] = pack2(sacc[2 * kc + 1][0], sacc[2 * kc + 1][1]);
            pA[kc][3] = pack2(sacc[2 * kc + 1][2], sacc[2 * kc + 1][3]);
        }

        // ---- O += P @ V, pipelined ----
        {
            uint32_t bb2[2][4];
            ldsm4t(vbuf + vOff, bb2[0]);
#pragma unroll
            for (int it = 0; it < 32; it++) {
                if (it + 1 < 32) {
                    int kc2 = (it + 1) >> 2, nip2 = (it + 1) & 3;
                    ldsm4t(vbuf + vOff + (kc2 * 16 * FK_STR + nip2 * 16) * 2,
                           bb2[(it + 1) & 1]);
                }
                int kc = it >> 2, nip = it & 3;
                mma_f16(o[2 * nip    ], pA[kc], &bb2[it & 1][0]);
                mma_f16(o[2 * nip + 1], pA[kc], &bb2[it & 1][2]);
            }
        }
    }

    float inv0 = 1.0f / lrun0;
    float inv1 = 1.0f / lrun1;
    int r0 = m0 + warp * 16 + grp;
    __half* cb = ctx + ((size_t)b * SEQ) * DMODEL + h * HEADDIM;
#pragma unroll
    for (int ni = 0; ni < 8; ni++) {
        int col = ni * 8 + 2 * tig;
        *(__half2*)(cb + (size_t)(r0    ) * DMODEL + col) =
            __floats2half2_rn(o[ni][0] * inv0, o[ni][1] * inv0);
        *(__half2*)(cb + (size_t)(r0 + 8) * DMODEL + col) =
            __floats2half2_rn(o[ni][2] * inv1, o[ni][3] * inv1);
    }
}

// ---------------------------------------------------------------------------
// Fused residual + LayerNorm: out = LN(a + b) * g + be.
// a, b both half (residual stream carried in half). Writes optional fp32
// `outf` and/or half `outh`.
// ---------------------------------------------------------------------------
__global__ __launch_bounds__(256)
void ln_kernel(const __half* __restrict__ a, const __half* __restrict__ b,
               const float* __restrict__ g, const float* __restrict__ be,
               float* __restrict__ outf, __half* __restrict__ outh)
{
    const int D = DMODEL;
    size_t row = blockIdx.x;
    const __half* pa = a + row * D;
    const __half* pb = b + row * D;
    int tid = threadIdx.x;
    __shared__ float red[256];

    float x[4];
    float s = 0.0f;
#pragma unroll
    for (int i = 0; i < 4; i++) {
        int c = tid + i * 256;
        x[i] = __half2float(pa[c]) + __half2float(pb[c]);
        s += x[i];
    }
    red[tid] = s;
    __syncthreads();
    for (int t = 128; t > 0; t >>= 1) {
        if (tid < t) red[tid] += red[tid + t];
        __syncthreads();
    }
    float mu = red[0] * (1.0f / D);
    __syncthreads();

    float v = 0.0f;
#pragma unroll
    for (int i = 0; i < 4; i++) {
        float d = x[i] - mu;
        v += d * d;
    }
    red[tid] = v;
    __syncthreads();
    for (int t = 128; t > 0; t >>= 1) {
        if (tid < t) red[tid] += red[tid + t];
        __syncthreads();
    }
    float var = red[0] * (1.0f / D);
    float r = rsqrtf(var + 1e-5f);
#pragma unroll
    for (int i = 0; i < 4; i++) {
        int c = tid + i * 256;
        float y = (x[i] - mu) * r * g[c] + be[c];
        if (outf) outf[row * D + c] = y;
        if (outh) outh[row * D + c] = __float2half_rn(y);
    }
}

// ---------------------------------------------------------------------------
// Host-side launch
// ---------------------------------------------------------------------------
static void* symptr_v(const void* sym)
{
    void* p = nullptr;
    cudaGetSymbolAddress(&p, sym);
    return p;
}

extern "C" void kernel_launch(void* const* d_in, const int* in_sizes, int n_in,
                              void* d_out, int out_size)
{
    const float* src = (const float*)d_in[0];
    const float* tau = (const float*)d_in[1];
    const float* Wq  = (const float*)d_in[2];
    const float* bq  = (const float*)d_in[3];
    const float* Wk  = (const float*)d_in[4];
    const float* bk  = (const float*)d_in[5];
    const float* Wv  = (const float*)d_in[6];
    const float* bv  = (const float*)d_in[7];
    const float* Wo  = (const float*)d_in[8];
    const float* bo  = (const float*)d_in[9];
    const float* W1  = (const float*)d_in[10];
    const float* b1  = (const float*)d_in[11];
    const float* W2  = (const float*)d_in[12];
    const float* b2  = (const float*)d_in[13];
    const float* g1  = (const float*)d_in[14];
    const float* be1 = (const float*)d_in[15];
    const float* g2  = (const float*)d_in[16];
    const float* be2 = (const float*)d_in[17];
    float* out = (float*)d_out;

    __half* srch = (__half*)symptr_v(g_srch);
    __half* qh   = (__half*)symptr_v(g_qh);
    __half* kh   = (__half*)symptr_v(g_kh);
    __half* vh   = (__half*)symptr_v(g_vh);
    __half* ctxh = (__half*)symptr_v(g_ctxh);
    __half* h1h  = (__half*)symptr_v(g_h1h);
    __half* f1h  = (__half*)symptr_v(g_f1h);
    __half* aoh  = (__half*)symptr_v(g_aoh);
    __half* f2h  = (__half*)symptr_v(g_f2h2);
    __half* wqH  = (__half*)symptr_v(g_wqH);
    __half* wkH  = (__half*)symptr_v(g_wkH);
    __half* wvH  = (__half*)symptr_v(g_wvH);
    __half* woH  = (__half*)symptr_v(g_woH);
    __half* w1H  = (__half*)symptr_v(g_w1H);
    __half* w2H  = (__half*)symptr_v(g_w2H);

    cudaFuncSetAttribute(flash_kernel,
                         cudaFuncAttributeMaxDynamicSharedMemorySize, FA_SMEM_BYTES);
    cudaFuncSetAttribute(hgemm<true,  false>,
                         cudaFuncAttributeMaxDynamicSharedMemorySize, GM_SMEM_BYTES);
    cudaFuncSetAttribute(hgemm<false, false>,
                         cudaFuncAttributeMaxDynamicSharedMemorySize, GM_SMEM_BYTES);
    cudaFuncSetAttribute(hgemm<false, true>,
                         cudaFuncAttributeMaxDynamicSharedMemorySize, GM_SMEM_BYTES);

    // ---- prep: single fused f2h of all weights + src ----
    {
        const int nW = DMODEL * DMODEL / 4;        // 262144
        const int nF = DMODEL * DFF / 4;           // 1048576
        const int nS = TOKENS * DMODEL / 4;        // 1048576
        F2HJob job;
        job.in[0] = (const float4*)Wq;  job.out[0] = (__half2*)wqH;
        job.in[1] = (const float4*)Wk;  job.out[1] = (__half2*)wkH;
        job.in[2] = (const float4*)Wv;  job.out[2] = (__half2*)wvH;
        job.in[3] = (const float4*)Wo;  job.out[3] = (__half2*)woH;
        job.in[4] = (const float4*)W1;  job.out[4] = (__half2*)w1H;
        job.in[5] = (const float4*)W2;  job.out[5] = (__half2*)w2H;
        job.in[6] = (const float4*)src; job.out[6] = (__half2*)srch;
        int acc = 0;
        int sizes[7] = { nW, nW, nW, nW, nF, nF, nS };
        for (int s = 0; s < 7; s++) { acc += sizes[s]; job.end[s] = acc; }
        f2h_all_kernel<<<(acc + 255) / 256, 256>>>(job);
    }

    // ---- QKV (+RoPE, q pre-scaled) ----
    hgemm<true, false>
        <<<dim3(DMODEL / 128, TOKENS / 128, 3), 256, GM_SMEM_BYTES>>>(
        TOKENS, DMODEL, DMODEL, srch, wqH, wkH, wvH,
        qh, kh, vh, DMODEL, bq, bk, bv, tau);

    // ---- flash attention -> ctx (half) ----
    flash_kernel<<<dim3(SEQ / 128, BATCH * NHEADS), 256, FA_SMEM_BYTES>>>(
        qh, kh, vh, ctxh);

    // ---- output projection -> aoh (half) ----
    hgemm<false, false>
        <<<dim3(DMODEL / 128, TOKENS / 128, 1), 256, GM_SMEM_BYTES>>>(
        TOKENS, DMODEL, DMODEL, ctxh, woH, nullptr, nullptr,
        aoh, nullptr, nullptr, DMODEL, bo, nullptr, nullptr, nullptr);

    // ---- LN1: h1 = LN(srch + aoh) -> half only ----
    ln_kernel<<<TOKENS, 256>>>(srch, aoh, g1, be1, nullptr, h1h);

    // ---- FFN1 (GELU) -> f1 (half) ----
    hgemm<false, true>
        <<<dim3(DFF / 128, TOKENS / 128, 1), 256, GM_SMEM_BYTES>>>(
        TOKENS, DFF, DMODEL, h1h, w1H, nullptr, nullptr,
        f1h, nullptr, nullptr, DFF, b1, nullptr, nullptr, nullptr);

    // ---- FFN2 -> f2 (half) ----
    hgemm<false, false>
        <<<dim3(DMODEL / 128, TOKENS / 128, 1), 256, GM_SMEM_BYTES>>>(
        TOKENS, DMODEL, DFF, f1h, w2H, nullptr, nullptr,
        f2h, nullptr, nullptr, DMODEL, b2, nullptr, nullptr, nullptr);

    // ---- LN2: out = LN(h1h + f2h) -> fp32 ----
    ln_kernel<<<TOKENS, 256>>>(h1h, f2h, g2, be2, out, nullptr);

    (void)in_sizes; (void)n_in; (void)out_size;
}

// round 17
// speedup vs baseline: 1.2142x; 1.0181x over previous
#include <cuda_runtime.h>
#include <cuda_fp16.h>
#include <math.h>
#include <cstdint>

// ---------------------------------------------------------------------------
// Problem constants
// ---------------------------------------------------------------------------
#define BATCH   2
#define SEQ     2048
#define DMODEL  1024
#define NHEADS  16
#define HEADDIM 64
#define DFF     4096
#define TOKENS  (BATCH * SEQ)          // 4096

// ---------------------------------------------------------------------------
// Scratch (static device allocations)
// ---------------------------------------------------------------------------
__device__ __half g_srch[TOKENS * DMODEL];
__device__ __half g_qh  [TOKENS * DMODEL];
__device__ __half g_kh  [TOKENS * DMODEL];
__device__ __half g_vh  [TOKENS * DMODEL];
__device__ __half g_ctxh[TOKENS * DMODEL];
__device__ __half g_h1h [TOKENS * DMODEL];
__device__ __half g_f1h [(size_t)TOKENS * DFF];
__device__ __half g_aoh [TOKENS * DMODEL];
__device__ __half g_f2h2[TOKENS * DMODEL];
// half weights, natural [K][N] layout
__device__ __half g_wqH[DMODEL * DMODEL];
__device__ __half g_wkH[DMODEL * DMODEL];
__device__ __half g_wvH[DMODEL * DMODEL];
__device__ __half g_woH[DMODEL * DMODEL];
__device__ __half g_w1H[(size_t)DMODEL * DFF];
__device__ __half g_w2H[(size_t)DFF * DMODEL];

// ---------------------------------------------------------------------------
// PTX helpers
// ---------------------------------------------------------------------------
__device__ __forceinline__ uint32_t smem_u32(const void* p) {
    return (uint32_t)__cvta_generic_to_shared(p);
}
__device__ __forceinline__ void cp16(uint32_t s, const void* g) {
    asm volatile("cp.async.cg.shared.global [%0], [%1], 16;" :: "r"(s), "l"(g));
}
__device__ __forceinline__ void cp_commit() {
    asm volatile("cp.async.commit_group;");
}
template<int N>
__device__ __forceinline__ void cp_wait() {
    asm volatile("cp.async.wait_group %0;" :: "n"(N));
}
__device__ __forceinline__ uint32_t pack2(float lo, float hi) {
    __half2 h = __floats2half2_rn(lo, hi);
    return *reinterpret_cast<uint32_t*>(&h);
}
__device__ __forceinline__ void ldsm4(uint32_t addr, uint32_t* r) {
    asm volatile("ldmatrix.sync.aligned.m8n8.x4.shared.b16 {%0,%1,%2,%3}, [%4];"
        : "=r"(r[0]), "=r"(r[1]), "=r"(r[2]), "=r"(r[3]) : "r"(addr));
}
__device__ __forceinline__ void ldsm4t(uint32_t addr, uint32_t* r) {
    asm volatile("ldmatrix.sync.aligned.m8n8.x4.trans.shared.b16 {%0,%1,%2,%3}, [%4];"
        : "=r"(r[0]), "=r"(r[1]), "=r"(r[2]), "=r"(r[3]) : "r"(addr));
}
__device__ __forceinline__ void mma_f16(float* c, const uint32_t* a, const uint32_t* b) {
    asm volatile(
        "mma.sync.aligned.m16n8k16.row.col.f32.f16.f16.f32 "
        "{%0,%1,%2,%3}, {%4,%5,%6,%7}, {%8,%9}, {%0,%1,%2,%3};"
        : "+f"(c[0]), "+f"(c[1]), "+f"(c[2]), "+f"(c[3])
        : "r"(a[0]), "r"(a[1]), "r"(a[2]), "r"(a[3]), "r"(b[0]), "r"(b[1]));
}

// ---------------------------------------------------------------------------
// FP16 GEMM: C[M,N] = A[M,K](half) @ W[K,N](half) + bias, half output.
// BM=128, BN=128, BK=32, 8 warps (warp tile 64x32), 2 CTAs/SM.
// 4-stage cp.async ring, interleaved LDSM prefetch, correct waits.
// (unchanged — the verified best GEMM config)
// ---------------------------------------------------------------------------
#define GM_ASTR 40                       // A smem row stride (halves)
#define GM_BSTR 136                      // B smem row stride (halves)
#define GM_AH   (128 * GM_ASTR)          // 5120 halves
#define GM_BH   (32 * GM_BSTR)           // 4352 halves
#define GM_STG  (GM_AH + GM_BH)          // 9472 halves / stage
#define GM_SMEM_BYTES (4 * GM_STG * 2)   // 75776 (x2 CTAs = 148 KB/SM)

template<bool QKV, bool GELU>
__global__ __launch_bounds__(256, 2)
void hgemm(int M, int N, int K,
           const __half* __restrict__ A,
           const __half* __restrict__ W0, const __half* __restrict__ W1_,
           const __half* __restrict__ W2_,
           __half* __restrict__ Ch0, __half* __restrict__ Ch1,
           __half* __restrict__ Ch2,
           int ldc,
           const float* __restrict__ bias0, const float* __restrict__ bias1,
           const float* __restrict__ bias2,
           const float* __restrict__ tau)
{
    extern __shared__ __half hsm[];

    const __half* W    = W0;
    __half*       Ch   = Ch0;
    const float*  bias = bias0;
    bool rope = false;
    float oscale = 1.0f;
    if (QKV) {
        int z = blockIdx.z;
        if (z == 1)      { W = W1_; Ch = Ch1; bias = bias1; }
        else if (z == 2) { W = W2_; Ch = Ch2; bias = bias2; }
        rope = (z < 2);
        if (z == 0) oscale = 0.125f;
    }

    const int tid  = threadIdx.x;
    const int lane = tid & 31;
    const int warp = tid >> 5;
    const int grp  = lane >> 2;
    const int tig  = lane & 3;
    const int wm0  = (warp >> 2) * 64;    // 0 or 64
    const int wn0  = (warp & 3) * 32;     // 0,32,64,96
    const int m0 = blockIdx.y * 128;
    const int n0 = blockIdx.x * 128;

    const uint32_t sbase = smem_u32(hsm);
    const uint32_t aOff = ((wm0 + (lane & 15)) * GM_ASTR + (lane >> 4) * 8) * 2;
    const int g8 = lane >> 3, r8 = lane & 7;
    const uint32_t bOff = (((g8 & 1) * 8 + r8) * GM_BSTR + wn0 + (g8 >> 1) * 8) * 2;

    float acc[4][4][4];
#pragma unroll
    for (int mi = 0; mi < 4; mi++)
#pragma unroll
        for (int ni = 0; ni < 4; ni++)
#pragma unroll
            for (int e = 0; e < 4; e++) acc[mi][ni][e] = 0.0f;

    auto load_stage = [&](int s) {
        uint32_t ab = sbase + (s & 3) * GM_STG * 2;
        uint32_t bb = ab + GM_AH * 2;
        int k0 = s * 32;
#pragma unroll
        for (int l = 0; l < 2; l++) {
            int c = tid + l * 256;
            int m = c >> 2, ch = c & 3;
            cp16(ab + (m * GM_ASTR + ch * 8) * 2,
                 A + (size_t)(m0 + m) * K + k0 + ch * 8);
        }
#pragma unroll
        for (int l = 0; l < 2; l++) {
            int c = tid + l * 256;
            int kk = c >> 4, nq = c & 15;
            cp16(bb + (kk * GM_BSTR + nq * 8) * 2,
                 W + (size_t)(k0 + kk) * N + n0 + nq * 8);
        }
        cp_commit();
    };

    // register fragment double-buffer
    uint32_t af[2][4][4], bf[2][4][2];

    auto load_frags = [&](int s, int kk, int p) {
        uint32_t ab = sbase + (s & 3) * GM_STG * 2;
        uint32_t bb = ab + GM_AH * 2;
#pragma unroll
        for (int mi = 0; mi < 4; mi++)
            ldsm4(ab + aOff + (mi * 16 * GM_ASTR + kk) * 2, af[p][mi]);
#pragma unroll
        for (int nip = 0; nip < 2; nip++)
            ldsm4t(bb + bOff + (kk * GM_BSTR + nip * 16) * 2, &bf[p][2 * nip][0]);
    };

    // 16 MMAs on buffer p; interleave the 6 LDSMs for (s_ld, kk_ld) -> buffer q.
    auto mma_block = [&](int p, int q, int s_ld, int kk_ld) {
        uint32_t ab = sbase + (s_ld & 3) * GM_STG * 2;
        uint32_t bb = ab + GM_AH * 2;
        mma_f16(acc[0][0], af[p][0], bf[p][0]);
        mma_f16(acc[0][1], af[p][0], bf[p][1]);
        ldsm4(ab + aOff + (0 * 16 * GM_ASTR + kk_ld) * 2, af[q][0]);
        mma_f16(acc[0][2], af[p][0], bf[p][2]);
        mma_f16(acc[0][3], af[p][0], bf[p][3]);
        ldsm4(ab + aOff + (1 * 16 * GM_ASTR + kk_ld) * 2, af[q][1]);
        mma_f16(acc[1][0], af[p][1], bf[p][0]);
        mma_f16(acc[1][1], af[p][1], bf[p][1]);
        ldsm4(ab + aOff + (2 * 16 * GM_ASTR + kk_ld) * 2, af[q][2]);
        mma_f16(acc[1][2], af[p][1], bf[p][2]);
        mma_f16(acc[1][3], af[p][1], bf[p][3]);
        ldsm4(ab + aOff + (3 * 16 * GM_ASTR + kk_ld) * 2, af[q][3]);
        mma_f16(acc[2][0], af[p][2], bf[p][0]);
        mma_f16(acc[2][1], af[p][2], bf[p][1]);
        ldsm4t(bb + bOff + (kk_ld * GM_BSTR + 0) * 2, &bf[q][0][0]);
        mma_f16(acc[2][2], af[p][2], bf[p][2]);
        mma_f16(acc[2][3], af[p][2], bf[p][3]);
        ldsm4t(bb + bOff + (kk_ld * GM_BSTR + 16) * 2, &bf[q][2][0]);
        mma_f16(acc[3][0], af[p][3], bf[p][0]);
        mma_f16(acc[3][1], af[p][3], bf[p][1]);
        mma_f16(acc[3][2], af[p][3], bf[p][2]);
        mma_f16(acc[3][3], af[p][3], bf[p][3]);
    };

    const int S = K / 32;
    load_stage(0); load_stage(1); load_stage(2);
    cp_wait<2>();          // stage 0 complete
    __syncthreads();
    load_frags(0, 0, 0);

    for (int s = 0; s < S; s++) {
        // committed groups so far: stages 0..min(s+2, S-1).
        // need stages <= s+1 complete (phase B prefetches stage s+1).
        if (s < S - 2) cp_wait<1>();
        else           cp_wait<0>();
        __syncthreads();              // visibility + ring-slot (s+3)%4 reuse
        if (s + 3 < S) load_stage(s + 3);
        mma_block(0, 1, s, 16);       // compute (s,0),  prefetch (s,16)
        mma_block(1, 0, s + 1, 0);    // compute (s,16), prefetch (s+1,0)
        // (s == S-1: phantom prefetch of stage S, never consumed)
    }

    // ---- epilogue (half output) ----
#pragma unroll
    for (int mi = 0; mi < 4; mi++) {
#pragma unroll
        for (int h = 0; h < 2; h++) {
            int row = m0 + wm0 + mi * 16 + grp + h * 8;
            float t = 0.0f;
            if (QKV) t = tau[row];
#pragma unroll
            for (int ni = 0; ni < 4; ni++) {
                int gcol = n0 + wn0 + ni * 8 + 2 * tig;
                float v0 = acc[mi][ni][h * 2 + 0];
                float v1 = acc[mi][ni][h * 2 + 1];
                if (bias) { v0 += bias[gcol]; v1 += bias[gcol + 1]; }
                if (GELU) {
                    v0 = 0.5f * v0 * (1.0f + erff(v0 * 0.7071067811865475f));
                    v1 = 0.5f * v1 * (1.0f + erff(v1 * 0.7071067811865475f));
                }
                if (QKV && rope) {
                    int j = (gcol & 63) >> 1;
                    float inv = __expf(-0.28782313662425572f * (float)j);
                    float sn, cs;
                    sincosf(t * inv, &sn, &cs);
                    float r0 = v0 * cs - v1 * sn;
                    float r1 = v1 * cs + v0 * sn;
                    v0 = r0 * oscale; v1 = r1 * oscale;
                }
                *(__half2*)(Ch + (size_t)row * ldc + gcol) =
                    __floats2half2_rn(v0, v1);
            }
        }
    }
}

// ---------------------------------------------------------------------------
// Fused float->half conversion of all 7 buffers; 2 float4 per thread.
// ---------------------------------------------------------------------------
struct F2HJob {
    const float4* in[7];
    __half2*      out[7];
    int           end[7];   // cumulative end offsets (in float4 units)
};

__global__ __launch_bounds__(256)
void f2h_all_kernel(F2HJob job, int total)
{
    int base_i = (blockIdx.x * 256 + threadIdx.x) * 2;
#pragma unroll
    for (int u = 0; u < 2; u++) {
        int i = base_i + u;
        if (i >= total) return;
        int seg = 0, base = 0;
#pragma unroll
        for (int s = 0; s < 7; s++) {
            if (i >= job.end[s]) { seg = s + 1; base = job.end[s]; }
        }
        int off = i - base;
        float4 v = job.in[seg][off];
        job.out[seg][2 * off]     = __floats2half2_rn(v.x, v.y);
        job.out[seg][2 * off + 1] = __floats2half2_rn(v.z, v.w);
    }
}

// ---------------------------------------------------------------------------
// FP16 flash attention with ldmatrix + cp.async K/V double buffers.
// (unchanged)
// ---------------------------------------------------------------------------
#define FK_STR  72
#define FT_H    (128 * FK_STR)
#define FA_SMEM_BYTES (4 * FT_H * 2)      // 73728

__global__ __launch_bounds__(256)
void flash_kernel(const __half* __restrict__ q, const __half* __restrict__ k,
                  const __half* __restrict__ v, __half* __restrict__ ctx)
{
    extern __shared__ __half fsm[];
    const uint32_t sbase = smem_u32(fsm);

    const int tid  = threadIdx.x;
    const int lane = tid & 31;
    const int warp = tid >> 5;
    const int grp  = lane >> 2;
    const int tig  = lane & 3;
    const int g8 = lane >> 3, r8 = lane & 7;

    const int m0 = blockIdx.x * 128;
    const int bh = blockIdx.y;
    const int b  = bh >> 4;
    const int h  = bh & 15;

    const __half* qb = q + ((size_t)b * SEQ) * DMODEL + h * HEADDIM;
    const __half* kb = k + ((size_t)b * SEQ) * DMODEL + h * HEADDIM;
    const __half* vb = v + ((size_t)b * SEQ) * DMODEL + h * HEADDIM;

    const uint32_t qOff = ((warp * 16 + (lane & 15)) * FK_STR + (lane >> 4) * 8) * 2;
    const uint32_t kOff = ((r8 + (g8 >> 1) * 8) * FK_STR + (g8 & 1) * 8) * 2;
    const uint32_t vOff = ((r8 + (g8 & 1) * 8) * FK_STR + (g8 >> 1) * 8) * 2;

#pragma unroll
    for (int l = 0; l < 4; l++) {
        int c = tid + l * 256;
        int r = c >> 3, ch = c & 7;
        cp16(sbase + (r * FK_STR + ch * 8) * 2,
             qb + (size_t)(m0 + r) * DMODEL + ch * 8);
    }
    cp_commit(); cp_wait<0>(); __syncthreads();

    uint32_t aq[4][4];
#pragma unroll
    for (int kc = 0; kc < 4; kc++)
        ldsm4(sbase + qOff + kc * 32, aq[kc]);
    __syncthreads();

    float o[8][4];
#pragma unroll
    for (int ni = 0; ni < 8; ni++)
#pragma unroll
        for (int e = 0; e < 4; e++) o[ni][e] = 0.0f;
    float mrun0 = -1e30f, mrun1 = -1e30f, lrun0 = 0.0f, lrun1 = 0.0f;

    auto load_kv = [&](int t) {
        uint32_t kd = sbase + (t & 1) * FT_H * 2;
        uint32_t vd = sbase + (2 + (t & 1)) * FT_H * 2;
#pragma unroll
        for (int l = 0; l < 4; l++) {
            int c = tid + l * 256;
            int r = c >> 3, ch = c & 7;
            uint32_t so = (r * FK_STR + ch * 8) * 2;
            size_t  go = (size_t)(t * 128 + r) * DMODEL + ch * 8;
            cp16(kd + so, kb + go);
            cp16(vd + so, vb + go);
        }
        cp_commit();
    };

    load_kv(0);

    const int NTILE = SEQ / 128;
    for (int t = 0; t < NTILE; t++) {
        cp_wait<0>();
        __syncthreads();
        if (t + 1 < NTILE) load_kv(t + 1);

        uint32_t kbuf = sbase + (t & 1) * FT_H * 2;
        uint32_t vbuf = sbase + (2 + (t & 1)) * FT_H * 2;

        float sacc[16][4];
#pragma unroll
        for (int ni = 0; ni < 16; ni++)
#pragma unroll
            for (int e = 0; e < 4; e++) sacc[ni][e] = 0.0f;

        // ---- S = Q @ K^T, pipelined ----
        {
            uint32_t bf2[2][4];
            ldsm4(kbuf + kOff, bf2[0]);
#pragma unroll
            for (int it = 0; it < 32; it++) {
                if (it + 1 < 32) {
                    int kc2 = (it + 1) >> 3, nip2 = (it + 1) & 7;
                    ldsm4(kbuf + kOff + (nip2 * 16 * FK_STR + kc2 * 16) * 2,
                          bf2[(it + 1) & 1]);
                }
                int kc = it >> 3, nip = it & 7;
                mma_f16(sacc[2 * nip    ], aq[kc], &bf2[it & 1][0]);
                mma_f16(sacc[2 * nip + 1], aq[kc], &bf2[it & 1][2]);
            }
        }

        float tmax0 = -1e30f, tmax1 = -1e30f;
#pragma unroll
        for (int ni = 0; ni < 16; ni++) {
            tmax0 = fmaxf(tmax0, fmaxf(sacc[ni][0], sacc[ni][1]));
            tmax1 = fmaxf(tmax1, fmaxf(sacc[ni][2], sacc[ni][3]));
        }
        tmax0 = fmaxf(tmax0, __shfl_xor_sync(0xffffffffu, tmax0, 1));
        tmax0 = fmaxf(tmax0, __shfl_xor_sync(0xffffffffu, tmax0, 2));
        tmax1 = fmaxf(tmax1, __shfl_xor_sync(0xffffffffu, tmax1, 1));
        tmax1 = fmaxf(tmax1, __shfl_xor_sync(0xffffffffu, tmax1, 2));

        float nm0 = fmaxf(mrun0, tmax0);
        float nm1 = fmaxf(mrun1, tmax1);
        float sc0 = __expf(mrun0 - nm0);
        float sc1 = __expf(mrun1 - nm1);
        mrun0 = nm0; mrun1 = nm1;

        float sum0 = 0.0f, sum1 = 0.0f;
#pragma unroll
        for (int ni = 0; ni < 16; ni++) {
            sacc[ni][0] = __expf(sacc[ni][0] - nm0);
            sacc[ni][1] = __expf(sacc[ni][1] - nm0);
            sacc[ni][2] = __expf(sacc[ni][2] - nm1);
            sacc[ni][3] = __expf(sacc[ni][3] - nm1);
            sum0 += sacc[ni][0] + sacc[ni][1];
            sum1 += sacc[ni][2] + sacc[ni][3];
        }
        sum0 += __shfl_xor_sync(0xffffffffu, sum0, 1);
        sum0 += __shfl_xor_sync(0xffffffffu, sum0, 2);
        sum1 += __shfl_xor_sync(0xffffffffu, sum1, 1);
        sum1 += __shfl_xor_sync(0xffffffffu, sum1, 2);
        lrun0 = lrun0 * sc0 + sum0;
        lrun1 = lrun1 * sc1 + sum1;

#pragma unroll
        for (int ni = 0; ni < 8; ni++) {
            o[ni][0] *= sc0; o[ni][1] *= sc0;
            o[ni][2] *= sc1; o[ni][3] *= sc1;
        }

        uint32_t pA[8][4];
#pragma unroll
        for (int kc = 0; kc < 8; kc++) {
            pA[kc][0] = pack2(sacc[2 * kc    ][0], sacc[2 * kc    ][1]);
            pA[kc][1] = pack2(sacc[2 * kc    ][2], sacc[2 * kc    ][3]);
            pA[kc][2] = pack2(sacc[2 * kc + 1][0], sacc[2 * kc + 1][1]);
            pA[kc][3] = pack2(sacc[2 * kc + 1][2], sacc[2 * kc + 1][3]);
        }

        // ---- O += P @ V, pipelined ----
        {
            uint32_t bb2[2][4];
            ldsm4t(vbuf + vOff, bb2[0]);
#pragma unroll
            for (int it = 0; it < 32; it++) {
                if (it + 1 < 32) {
                    int kc2 = (it + 1) >> 2, nip2 = (it + 1) & 3;
                    ldsm4t(vbuf + vOff + (kc2 * 16 * FK_STR + nip2 * 16) * 2,
                           bb2[(it + 1) & 1]);
                }
                int kc = it >> 2, nip = it & 3;
                mma_f16(o[2 * nip    ], pA[kc], &bb2[it & 1][0]);
                mma_f16(o[2 * nip + 1], pA[kc], &bb2[it & 1][2]);
            }
        }
    }

    float inv0 = 1.0f / lrun0;
    float inv1 = 1.0f / lrun1;
    int r0 = m0 + warp * 16 + grp;
    __half* cb = ctx + ((size_t)b * SEQ) * DMODEL + h * HEADDIM;
#pragma unroll
    for (int ni = 0; ni < 8; ni++) {
        int col = ni * 8 + 2 * tig;
        *(__half2*)(cb + (size_t)(r0    ) * DMODEL + col) =
            __floats2half2_rn(o[ni][0] * inv0, o[ni][1] * inv0);
        *(__half2*)(cb + (size_t)(r0 + 8) * DMODEL + col) =
            __floats2half2_rn(o[ni][2] * inv1, o[ni][3] * inv1);
    }
}

// ---------------------------------------------------------------------------
// Fused residual + LayerNorm: out = LN(a + b) * g + be.
// Single-pass (sum + sumsq) with warp-shuffle reductions: 2 barriers total.
// ---------------------------------------------------------------------------
__global__ __launch_bounds__(256)
void ln_kernel(const __half* __restrict__ a, const __half* __restrict__ b,
               const float* __restrict__ g, const float* __restrict__ be,
               float* __restrict__ outf, __half* __restrict__ outh)
{
    const int D = DMODEL;
    size_t row = blockIdx.x;
    const __half* pa = a + row * D;
    const __half* pb = b + row * D;
    int tid  = threadIdx.x;
    int lane = tid & 31;
    int warp = tid >> 5;
    __shared__ float red[16];   // [8 warps][2]

    float x[4];
    float s = 0.0f, sq = 0.0f;
#pragma unroll
    for (int i = 0; i < 4; i++) {
        int c = tid + i * 256;
        x[i] = __half2float(pa[c]) + __half2float(pb[c]);
        s  += x[i];
        sq += x[i] * x[i];
    }
#pragma unroll
    for (int d = 16; d > 0; d >>= 1) {
        s  += __shfl_xor_sync(0xffffffffu, s,  d);
        sq += __shfl_xor_sync(0xffffffffu, sq, d);
    }
    if (lane == 0) { red[warp] = s; red[8 + warp] = sq; }
    __syncthreads();
    if (warp == 0) {
        float ws  = (lane < 8) ? red[lane]     : 0.0f;
        float wsq = (lane < 8) ? red[8 + lane] : 0.0f;
#pragma unroll
        for (int d = 4; d > 0; d >>= 1) {
            ws  += __shfl_xor_sync(0xffffffffu, ws,  d);
            wsq += __shfl_xor_sync(0xffffffffu, wsq, d);
        }
        if (lane == 0) { red[0] = ws; red[1] = wsq; }
    }
    __syncthreads();
    float mu  = red[0] * (1.0f / D);
    float var = red[1] * (1.0f / D) - mu * mu;
    float r = rsqrtf(var + 1e-5f);
#pragma unroll
    for (int i = 0; i < 4; i++) {
        int c = tid + i * 256;
        float y = (x[i] - mu) * r * g[c] + be[c];
        if (outf) outf[row * D + c] = y;
        if (outh) outh[row * D + c] = __float2half_rn(y);
    }
}

// ---------------------------------------------------------------------------
// Host-side launch
// ---------------------------------------------------------------------------
static void* symptr_v(const void* sym)
{
    void* p = nullptr;
    cudaGetSymbolAddress(&p, sym);
    return p;
}

extern "C" void kernel_launch(void* const* d_in, const int* in_sizes, int n_in,
                              void* d_out, int out_size)
{
    const float* src = (const float*)d_in[0];
    const float* tau = (const float*)d_in[1];
    const float* Wq  = (const float*)d_in[2];
    const float* bq  = (const float*)d_in[3];
    const float* Wk  = (const float*)d_in[4];
    const float* bk  = (const float*)d_in[5];
    const float* Wv  = (const float*)d_in[6];
    const float* bv  = (const float*)d_in[7];
    const float* Wo  = (const float*)d_in[8];
    const float* bo  = (const float*)d_in[9];
    const float* W1  = (const float*)d_in[10];
    const float* b1  = (const float*)d_in[11];
    const float* W2  = (const float*)d_in[12];
    const float* b2  = (const float*)d_in[13];
    const float* g1  = (const float*)d_in[14];
    const float* be1 = (const float*)d_in[15];
    const float* g2  = (const float*)d_in[16];
    const float* be2 = (const float*)d_in[17];
    float* out = (float*)d_out;

    __half* srch = (__half*)symptr_v(g_srch);
    __half* qh   = (__half*)symptr_v(g_qh);
    __half* kh   = (__half*)symptr_v(g_kh);
    __half* vh   = (__half*)symptr_v(g_vh);
    __half* ctxh = (__half*)symptr_v(g_ctxh);
    __half* h1h  = (__half*)symptr_v(g_h1h);
    __half* f1h  = (__half*)symptr_v(g_f1h);
    __half* aoh  = (__half*)symptr_v(g_aoh);
    __half* f2h  = (__half*)symptr_v(g_f2h2);
    __half* wqH  = (__half*)symptr_v(g_wqH);
    __half* wkH  = (__half*)symptr_v(g_wkH);
    __half* wvH  = (__half*)symptr_v(g_wvH);
    __half* woH  = (__half*)symptr_v(g_woH);
    __half* w1H  = (__half*)symptr_v(g_w1H);
    __half* w2H  = (__half*)symptr_v(g_w2H);

    cudaFuncSetAttribute(flash_kernel,
                         cudaFuncAttributeMaxDynamicSharedMemorySize, FA_SMEM_BYTES);
    cudaFuncSetAttribute(hgemm<true,  false>,
                         cudaFuncAttributeMaxDynamicSharedMemorySize, GM_SMEM_BYTES);
    cudaFuncSetAttribute(hgemm<false, false>,
                         cudaFuncAttributeMaxDynamicSharedMemorySize, GM_SMEM_BYTES);
    cudaFuncSetAttribute(hgemm<false, true>,
                         cudaFuncAttributeMaxDynamicSharedMemorySize, GM_SMEM_BYTES);

    // ---- prep: single fused f2h of all weights + src (2 float4/thread) ----
    {
        const int nW = DMODEL * DMODEL / 4;        // 262144
        const int nF = DMODEL * DFF / 4;           // 1048576
        const int nS = TOKENS * DMODEL / 4;        // 1048576
        F2HJob job;
        job.in[0] = (const float4*)Wq;  job.out[0] = (__half2*)wqH;
        job.in[1] = (const float4*)Wk;  job.out[1] = (__half2*)wkH;
        job.in[2] = (const float4*)Wv;  job.out[2] = (__half2*)wvH;
        job.in[3] = (const float4*)Wo;  job.out[3] = (__half2*)woH;
        job.in[4] = (const float4*)W1;  job.out[4] = (__half2*)w1H;
        job.in[5] = (const float4*)W2;  job.out[5] = (__half2*)w2H;
        job.in[6] = (const float4*)src; job.out[6] = (__half2*)srch;
        int acc = 0;
        int sizes[7] = { nW, nW, nW, nW, nF, nF, nS };
        for (int s = 0; s < 7; s++) { acc += sizes[s]; job.end[s] = acc; }
        int threads_needed = (acc + 1) / 2;
        f2h_all_kernel<<<(threads_needed + 255) / 256, 256>>>(job, acc);
    }

    // ---- QKV (+RoPE, q pre-scaled) ----
    hgemm<true, false>
        <<<dim3(DMODEL / 128, TOKENS / 128, 3), 256, GM_SMEM_BYTES>>>(
        TOKENS, DMODEL, DMODEL, srch, wqH, wkH, wvH,
        qh, kh, vh, DMODEL, bq, bk, bv, tau);

    // ---- flash attention -> ctx (half) ----
    flash_kernel<<<dim3(SEQ / 128, BATCH * NHEADS), 256, FA_SMEM_BYTES>>>(
        qh, kh, vh, ctxh);

    // ---- output projection -> aoh (half) ----
    hgemm<false, false>
        <<<dim3(DMODEL / 128, TOKENS / 128, 1), 256, GM_SMEM_BYTES>>>(
        TOKENS, DMODEL, DMODEL, ctxh, woH, nullptr, nullptr,
        aoh, nullptr, nullptr, DMODEL, bo, nullptr, nullptr, nullptr);

    // ---- LN1: h1 = LN(srch + aoh) -> half only ----
    ln_kernel<<<TOKENS, 256>>>(srch, aoh, g1, be1, nullptr, h1h);

    // ---- FFN1 (GELU) -> f1 (half) ----
    hgemm<false, true>
        <<<dim3(DFF / 128, TOKENS / 128, 1), 256, GM_SMEM_BYTES>>>(
        TOKENS, DFF, DMODEL, h1h, w1H, nullptr, nullptr,
        f1h, nullptr, nullptr, DFF, b1, nullptr, nullptr, nullptr);

    // ---- FFN2 -> f2 (half) ----
    hgemm<false, false>
        <<<dim3(DMODEL / 128, TOKENS / 128, 1), 256, GM_SMEM_BYTES>>>(
        TOKENS, DMODEL, DFF, f1h, w2H, nullptr, nullptr,
        f2h, nullptr, nullptr, DMODEL, b2, nullptr, nullptr, nullptr);

    // ---- LN2: out = LN(h1h + f2h) -> fp32 ----
    ln_kernel<<<TOKENS, 256>>>(h1h, f2h, g2, be2, out, nullptr);

    (void)in_sizes; (void)n_in; (void)out_size;
}